// round 1
// baseline (speedup 1.0000x reference)
#include <cuda_runtime.h>
#include <math.h>

#define TILE_R   64
#define NTHREADS 256
#define KT       16
#define HID      256
#define FDIM     128
#define NEDGE    262144
#define NTRI     393216
#define MBINS    100

// ---- shared memory layout (float offsets) ----
#define SZ_WBUF  (2*KT*HID)       // 8192 floats  (double-buffered W chunk [16][256])
#define SZ_XBUF  (2*TILE_R*KT)    // 2048 floats  (double-buffered X chunk [64][16])
#define SZ_ACT   (TILE_R*HID)     // 16384 floats (activation tile [64][256])
#define OFF_WBUF 0
#define OFF_XBUF (OFF_WBUF + SZ_WBUF)
#define OFF_ACTA (OFF_XBUF + SZ_XBUF)
#define OFF_ACTB (OFF_ACTA + SZ_ACT)
#define OFF_MU   (OFF_ACTB + SZ_ACT)
#define OFF_W3   (OFF_MU + 128)
#define OFF_B3   (OFF_W3 + 3*HID)
#define OFF_IDX  (OFF_B3 + 4)
#define OFF_RN   (OFF_IDX + 3*TILE_R)
#define OFF_CS   (OFF_RN + 2*TILE_R)
#define OFF_SS   (OFF_CS + TILE_R)
#define SMEM_FLOATS (OFF_SS + TILE_R)
#define SMEM_BYTES  (SMEM_FLOATS*4)

typedef unsigned long long u64;

__device__ __forceinline__ u64 pack2(float a, float b){
  u64 r; asm("mov.b64 %0, {%1, %2};" : "=l"(r) : "f"(a), "f"(b)); return r;
}
__device__ __forceinline__ void unpack2(u64 v, float& a, float& b){
  asm("mov.b64 {%0, %1}, %2;" : "=f"(a), "=f"(b) : "l"(v));
}
// Packed fp32x2 FMA: 2 MACs/instr -> restores full-rate fp32 on sm_100a
__device__ __forceinline__ void ffma2(u64& d, u64 a, u64 b){
  asm("fma.rn.f32x2 %0, %1, %2, %3;" : "=l"(d) : "l"(a), "l"(b), "l"(d));
}
__device__ __forceinline__ void cp16(float* dst, const float* src, int sz){
  unsigned d = (unsigned)__cvta_generic_to_shared(dst);
  asm volatile("cp.async.cg.shared.global [%0], [%1], 16, %2;"
               :: "r"(d), "l"(src), "r"(sz) : "memory");
}
__device__ __forceinline__ void cp_commit(){ asm volatile("cp.async.commit_group;" ::: "memory"); }
__device__ __forceinline__ void cp_wait1(){ asm volatile("cp.async.wait_group 1;" ::: "memory"); }
__device__ __forceinline__ void cp_wait0(){ asm volatile("cp.async.wait_group 0;" ::: "memory"); }

// C[64x256] += X_chunk[64xKT] @ W_chunk[KTx256]; per-thread 8 rows x 8 cols.
// X reads are warp-uniform (broadcast); W reads are 8B LDS, conflict-free.
__device__ __forceinline__ void gemm_chunk(const float* __restrict__ Xs, int xstride,
                                           const float* __restrict__ Ws,
                                           u64 (&acc)[8][4], int r0, int c0){
  #pragma unroll
  for (int kk = 0; kk < KT; kk++){
    u64 wv[4];
    const float* wrow = Ws + kk*HID + c0;
    #pragma unroll
    for (int q = 0; q < 4; q++)
      wv[q] = *reinterpret_cast<const u64*>(wrow + 2*q);
    #pragma unroll
    for (int i = 0; i < 8; i++){
      float x = Xs[(r0+i)*xstride + kk];
      u64 xd = pack2(x, x);
      #pragma unroll
      for (int q = 0; q < 4; q++) ffma2(acc[i][q], xd, wv[q]);
    }
  }
}

__device__ __forceinline__ void store_silu(u64 (&acc)[8][4], float* dst, int r0, int c0){
  #pragma unroll
  for (int i = 0; i < 8; i++){
    #pragma unroll
    for (int q = 0; q < 4; q++){
      float a, b; unpack2(acc[i][q], a, b);
      a = a * (1.0f / (1.0f + __expf(-a)));
      b = b * (1.0f / (1.0f + __expf(-b)));
      *reinterpret_cast<float2*>(dst + (r0+i)*HID + c0 + 2*q) = make_float2(a, b);
    }
  }
}

// KIN: true input width; KPAD: padded to KT multiple; NSEG: # of gathered h segments.
template<int KIN, int KPAD, int NSEG, bool TRIP>
__global__ void __launch_bounds__(NTHREADS, 1)
fused_mlp(const float* __restrict__ h,
          const int* __restrict__ i0, const int* __restrict__ i1, const int* __restrict__ i2,
          const float* __restrict__ rn0, const float* __restrict__ rn1,
          const float* __restrict__ cv, const float* __restrict__ sv,
          const float* __restrict__ mu,
          const float* __restrict__ W0g, const float* __restrict__ W1g,
          const float* __restrict__ W2g, const float* __restrict__ W3g,
          const float* __restrict__ b3g,
          float* __restrict__ out)
{
  extern __shared__ float sm[];
  float* Wbuf = sm + OFF_WBUF;
  float* Xbuf = sm + OFF_XBUF;
  float* actA = sm + OFF_ACTA;
  float* actB = sm + OFF_ACTB;
  float* mus  = sm + OFF_MU;
  float* w3s  = sm + OFF_W3;
  float* b3s  = sm + OFF_B3;
  int*   idxs = (int*)(sm + OFF_IDX);
  float* rns  = sm + OFF_RN;
  float* csm  = sm + OFF_CS;
  float* ssm  = sm + OFF_SS;

  const int tid  = threadIdx.x;
  const int row0 = blockIdx.x * TILE_R;

  // ---- per-block prologue: indices, norms, mu, W3/b3 into smem ----
  if (tid < TILE_R){
    idxs[tid]          = i0[row0 + tid];
    idxs[TILE_R + tid] = i1[row0 + tid];
    rns[tid]           = rn0[row0 + tid];
    if (TRIP){
      idxs[2*TILE_R + tid] = i2[row0 + tid];
      rns[TILE_R + tid]    = rn1[row0 + tid];
      csm[tid]             = cv[row0 + tid];
      ssm[tid]             = sv[row0 + tid];
    }
  }
  if (tid < MBINS) mus[tid] = mu[tid];
  for (int i = tid; i < 3*HID; i += NTHREADS) w3s[i] = W3g[i];
  if (tid < 3) b3s[tid] = b3g[tid];
  __syncthreads();

  u64 acc[8][4];
  const int r0 = (tid >> 5) * 8;   // row group (warp id * 8)
  const int c0 = (tid & 31) * 8;   // col group (lane * 8)

  // Stage a 16-row W chunk into Wbuf[buf] via cp.async (zero-fill past KIN rows)
  auto stageW = [&](const float* __restrict__ Wg, int wrows, int c, int buf){
    float* dstb = Wbuf + buf*(KT*HID);
    #pragma unroll
    for (int i = 0; i < 4; i++){
      int lin16 = tid + i*NTHREADS;               // 16B unit within chunk (0..1023)
      int row   = c*KT + (lin16 >> 6);            // 64 x 16B units per 256-wide row
      int sz    = (row < wrows) ? 16 : 0;
      const float* s = sz ? (Wg + (size_t)c*(KT*HID) + (size_t)lin16*4) : Wg;
      cp16(dstb + lin16*4, s, sz);
    }
  };

  // Stage a 16-col X0 chunk: cp.async gather from h, or compute RBF/cos/sin
  auto stageX = [&](int c, int buf){
    float* dstb = Xbuf + buf*(TILE_R*KT);
    int k0 = c*KT;
    if (k0 < NSEG*FDIM){
      int seg = k0 >> 7;
      int r = tid >> 2, part = tid & 3;
      const float* s = h + (size_t)idxs[seg*TILE_R + r]*FDIM + (k0 & (FDIM-1)) + part*4;
      cp16(dstb + r*KT + part*4, s, 16);
    } else {
      #pragma unroll
      for (int i = 0; i < 4; i++){
        int lin = tid*4 + i;          // == r*16 + kk
        int r = lin >> 4;
        int k = k0 + (lin & 15);
        float v = 0.0f;
        if (!TRIP){
          if (k < 2*FDIM + MBINS){
            float d = mus[k - 2*FDIM] - rns[r];
            v = __expf(-10.0f * d * d);
          }
        } else {
          if (k < 3*FDIM + MBINS){
            float d = mus[k - 3*FDIM] - rns[r];
            v = __expf(-10.0f * d * d);
          } else if (k < 3*FDIM + 2*MBINS){
            float d = mus[k - (3*FDIM + MBINS)] - rns[TILE_R + r];
            v = __expf(-10.0f * d * d);
          } else if (k == 3*FDIM + 2*MBINS){
            v = csm[r];
          } else if (k == 3*FDIM + 2*MBINS + 1){
            v = ssm[r];
          }
        }
        dstb[lin] = v;
      }
    }
  };

  // One GEMM layer with double-buffered cp.async W streaming (and X staging for layer0)
  auto runLayer = [&](const float* __restrict__ Wg, int wrows, int nc,
                      const float* __restrict__ Xsrc, bool l0){
    #pragma unroll
    for (int i = 0; i < 8; i++)
      #pragma unroll
      for (int q = 0; q < 4; q++) acc[i][q] = 0ULL;

    if (l0) stageX(0, 0);
    stageW(Wg, wrows, 0, 0);
    cp_commit();
    for (int c = 0; c < nc; c++){
      const int cb = c & 1;
      if (c + 1 < nc){
        if (l0) stageX(c+1, cb^1);
        stageW(Wg, wrows, c+1, cb^1);
        cp_commit();
        cp_wait1();
      } else {
        cp_wait0();
      }
      __syncthreads();
      if (l0) gemm_chunk(Xbuf + cb*(TILE_R*KT), KT,  Wbuf + cb*(KT*HID), acc, r0, c0);
      else    gemm_chunk(Xsrc + c*KT,           HID, Wbuf + cb*(KT*HID), acc, r0, c0);
      __syncthreads();
    }
  };

  // layer 0: [64 x KIN] @ W0 -> silu -> actA
  runLayer(W0g, KIN, KPAD/KT, (const float*)0, true);
  store_silu(acc, actA, r0, c0);
  // layer 1: actA @ W1 -> silu -> actB
  runLayer(W1g, HID, HID/KT, actA, false);
  store_silu(acc, actB, r0, c0);
  // layer 2: actB @ W2 -> silu -> actA
  runLayer(W2g, HID, HID/KT, actB, false);
  store_silu(acc, actA, r0, c0);
  __syncthreads();

  // layer 3: [64 x 256] @ W3[256x3] + b3
  if (tid < TILE_R*3){
    const int r = tid / 3, o = tid - r*3;
    float s = b3s[o];
    #pragma unroll 16
    for (int k = 0; k < HID; k++)
      s = fmaf(actA[r*HID + k], w3s[k*3 + o], s);
    out[(size_t)(row0 + r)*3 + o] = s;
  }
}

extern "C" void kernel_launch(void* const* d_in, const int* in_sizes, int n_in,
                              void* d_out, int out_size){
  const float* h     = (const float*)d_in[0];
  const int*   src   = (const int*)  d_in[1];
  const int*   dst   = (const int*)  d_in[2];
  const float* enorm = (const float*)d_in[3];
  const int*   tsrc  = (const int*)  d_in[4];
  const int*   tdi   = (const int*)  d_in[5];
  const int*   tdj   = (const int*)  d_in[6];
  const float* nij   = (const float*)d_in[7];
  const float* nik   = (const float*)d_in[8];
  const float* cosv  = (const float*)d_in[9];
  const float* sinv  = (const float*)d_in[10];
  const float* mu    = (const float*)d_in[11];
  const float* eW0   = (const float*)d_in[12];
  const float* eW1   = (const float*)d_in[13];
  const float* eW2   = (const float*)d_in[14];
  const float* eW3   = (const float*)d_in[15];
  const float* eb3   = (const float*)d_in[16];
  const float* tW0   = (const float*)d_in[17];
  const float* tW1   = (const float*)d_in[18];
  const float* tW2   = (const float*)d_in[19];
  const float* tW3   = (const float*)d_in[20];
  const float* tb3   = (const float*)d_in[21];
  float* out = (float*)d_out;

  cudaFuncSetAttribute(fused_mlp<356,368,2,false>,
                       cudaFuncAttributeMaxDynamicSharedMemorySize, SMEM_BYTES);
  cudaFuncSetAttribute(fused_mlp<586,592,3,true>,
                       cudaFuncAttributeMaxDynamicSharedMemorySize, SMEM_BYTES);

  // Edges: out rows [0, E)
  fused_mlp<356,368,2,false><<<NEDGE/TILE_R, NTHREADS, SMEM_BYTES>>>(
      h, src, dst, dst, enorm, enorm, enorm, enorm, mu,
      eW0, eW1, eW2, eW3, eb3, out);
  // Triplets: out rows [E, E+T)
  fused_mlp<586,592,3,true><<<NTRI/TILE_R, NTHREADS, SMEM_BYTES>>>(
      h, tsrc, tdi, tdj, nij, nik, cosv, sinv, mu,
      tW0, tW1, tW2, tW3, tb3, out + (size_t)NEDGE*3);
}

// round 4
// speedup vs baseline: 2.5384x; 2.5384x over previous
#include <cuda_runtime.h>
#include <cuda_bf16.h>
#include <stdint.h>

#define NEDGE 262144
#define NTRI  393216
#define TILE_M 128
#define NTH   512

// ---- smem byte offsets ----
#define W_BUF   0            // 3 slots x 16384 = 49152
#define X0_OFF  49152        // 2 slots x 32768 (hi 16K + lo 16K); overlaps ACT, dead after layer0
#define ACT_HI  49152        // 65536  (128 rows x 512B)
#define ACT_LO  114688       // 65536
#define MISC    181248       // fp32 act buffer (131584B from ACT_HI) ends at 180736 < MISC
#define OFF_W3  (MISC)       // 768 floats
#define OFF_B3  (MISC+3072)
#define OFF_MU  (MISC+3088)
#define OFF_IDX (MISC+3504)  // 3*128 ints
#define OFF_RN  (MISC+5040)  // 2*128 floats
#define OFF_CS  (MISC+6064)
#define OFF_SS  (MISC+6576)
#define SMEM_TOTAL (MISC+7168)   // 188416

// weight images: per layer, units of 32k x 256n bf16 (8192 u16 = 16KB),
// ordered [c0 hi, c0 lo, c1 hi, c1 lo, ...]; layers concatenated.
__device__ __align__(16) unsigned short g_wimg_e[458752]; // (24+16+16) units
__device__ __align__(16) unsigned short g_wimg_t[589824]; // (40+16+16) units

__device__ __forceinline__ uint32_t smem_u32(const void* p){
  uint32_t a;
  asm("{ .reg .u64 t; cvta.to.shared.u64 t, %1; cvt.u32.u64 %0, t; }" : "=r"(a) : "l"(p));
  return a;
}
__device__ __forceinline__ void cp16s(uint32_t dst, const void* src){
  asm volatile("cp.async.cg.shared.global [%0], [%1], 16;" :: "r"(dst), "l"(src) : "memory");
}
__device__ __forceinline__ void cp_commit(){ asm volatile("cp.async.commit_group;" ::: "memory"); }
template<int N> __device__ __forceinline__ void cp_wait(){ asm volatile("cp.async.wait_group %0;" :: "n"(N) : "memory"); }

__device__ __forceinline__ void ldsm4(uint32_t (&r)[4], uint32_t a){
  asm volatile("ldmatrix.sync.aligned.m8n8.x4.shared.b16 {%0,%1,%2,%3}, [%4];"
    : "=r"(r[0]), "=r"(r[1]), "=r"(r[2]), "=r"(r[3]) : "r"(a));
}
__device__ __forceinline__ void ldsm4t(uint32_t (&r)[4], uint32_t a){
  asm volatile("ldmatrix.sync.aligned.m8n8.x4.trans.shared.b16 {%0,%1,%2,%3}, [%4];"
    : "=r"(r[0]), "=r"(r[1]), "=r"(r[2]), "=r"(r[3]) : "r"(a));
}
__device__ __forceinline__ void mma_bf(float (&d)[4], const uint32_t (&a)[4], uint32_t b0, uint32_t b1){
  asm volatile("mma.sync.aligned.m16n8k16.row.col.f32.bf16.bf16.f32 "
    "{%0,%1,%2,%3}, {%4,%5,%6,%7}, {%8,%9}, {%0,%1,%2,%3};"
    : "+f"(d[0]), "+f"(d[1]), "+f"(d[2]), "+f"(d[3])
    : "r"(a[0]), "r"(a[1]), "r"(a[2]), "r"(a[3]), "r"(b0), "r"(b1));
}

__device__ __forceinline__ uint32_t pack_bf2(float x, float y){
  __nv_bfloat162 t = __floats2bfloat162_rn(x, y);
  return *(uint32_t*)&t;
}
// split pair into hi bf16x2 and lo bf16x2
__device__ __forceinline__ void split2(float x, float y, uint32_t& hv, uint32_t& lv){
  __nv_bfloat16 hx = __float2bfloat16(x), hy = __float2bfloat16(y);
  float lx = x - __bfloat162float(hx), ly = y - __bfloat162float(hy);
  hv = ((uint32_t)*(unsigned short*)&hx) | (((uint32_t)*(unsigned short*)&hy) << 16);
  lv = pack_bf2(lx, ly);
}
__device__ __forceinline__ float silu_f(float x){
  return __fdividef(x, 1.0f + __expf(-x));
}

// C[128x256] += A-chunk[128x32] @ W-chunk[32x256], per-warp tile 32x64
// aRB: A row stride bytes; kub: k-unit (16B) base within A row
__device__ __forceinline__ void pass_k32(float (&acc)[2][8][4],
    uint32_t aBase, int aRB, int kub, uint32_t wBase, int lane, int wn, int m15){
  #pragma unroll
  for (int ks = 0; ks < 2; ks++){
    const int ku = kub + ks*2 + (lane >> 4);
    uint32_t a0r[4], a1r[4];
    const uint32_t aa = aBase + (uint32_t)(m15 * aRB) + (uint32_t)((ku ^ (lane & 7)) << 4);
    ldsm4(a0r, aa);
    ldsm4(a1r, aa + 16 * aRB);
    const uint32_t wrow = wBase + (uint32_t)((ks*16 + (lane & 15)) * 512);
    #pragma unroll
    for (int jj = 0; jj < 4; jj++){
      const int nu = wn*8 + jj*2 + (lane >> 4);
      uint32_t br[4];
      ldsm4t(br, wrow + (uint32_t)((nu ^ (lane & 7)) << 4));
      mma_bf(acc[0][2*jj],   a0r, br[0], br[1]);
      mma_bf(acc[0][2*jj+1], a0r, br[2], br[3]);
      mma_bf(acc[1][2*jj],   a1r, br[0], br[1]);
      mma_bf(acc[1][2*jj+1], a1r, br[2], br[3]);
    }
  }
}

// ---- weight prep: fp32 [K][256] -> pre-swizzled bf16 hi/lo 16KB chunk units ----
__global__ void prep_w(const float* __restrict__ W, unsigned short* __restrict__ img,
                       int KIN, int Kpad){
  int gid = blockIdx.x * blockDim.x + threadIdx.x;
  if (gid >= Kpad * 256) return;
  int k = gid >> 8, n = gid & 255;
  float x = (k < KIN) ? W[k * 256 + n] : 0.0f;
  __nv_bfloat16 hb = __float2bfloat16(x);
  float rem = x - __bfloat162float(hb);
  __nv_bfloat16 lb = __float2bfloat16(rem);
  int c = k >> 5, kin = k & 31;
  int idx16 = kin * 256 + (((n >> 3) ^ (kin & 7)) << 3) + (n & 7);
  img[(size_t)(2*c)     * 8192 + idx16] = *(unsigned short*)&hb;
  img[(size_t)(2*c + 1) * 8192 + idx16] = *(unsigned short*)&lb;
}

// ---------------- fused MLP, mma.sync split-bf16 ----------------
template<bool TRIP, int KGATH, int NCH0>   // NCH0 = # of 32k W chunks for layer0 (even)
__global__ void __launch_bounds__(NTH, 1)
mlp_mma(const float* __restrict__ h,
        const int* __restrict__ i0, const int* __restrict__ i1, const int* __restrict__ i2,
        const float* __restrict__ rn0g, const float* __restrict__ rn1g,
        const float* __restrict__ cvg, const float* __restrict__ svg,
        const float* __restrict__ mug,
        const float* __restrict__ w3g, const float* __restrict__ b3g,
        const unsigned short* __restrict__ wimg,
        float* __restrict__ out)
{
  extern __shared__ __align__(1024) unsigned char sm[];
  const uint32_t sb = smem_u32(sm);
  const int tid = threadIdx.x, lane = tid & 31, wid = tid >> 5;
  const int wm = wid & 3, wn = wid >> 2;
  const int m15 = wm*32 + (lane & 15);
  const int row0 = blockIdx.x * TILE_M;

  float* w3s = (float*)(sm + OFF_W3);
  float* b3s = (float*)(sm + OFF_B3);
  float* mus = (float*)(sm + OFF_MU);
  int*   idxs = (int*)(sm + OFF_IDX);
  float* rns = (float*)(sm + OFF_RN);
  float* css = (float*)(sm + OFF_CS);
  float* sss = (float*)(sm + OFF_SS);

  if (tid < 128){
    idxs[tid]       = i0[row0 + tid];
    idxs[128 + tid] = i1[row0 + tid];
    rns[tid]        = rn0g[row0 + tid];
    if (TRIP){
      idxs[256 + tid] = i2[row0 + tid];
      rns[128 + tid]  = rn1g[row0 + tid];
      css[tid]        = cvg[row0 + tid];
      sss[tid]        = svg[row0 + tid];
    }
  }
  if (tid < 100) mus[tid] = mug[tid];
  for (int i = tid; i < 768; i += NTH) w3s[i] = w3g[i];
  if (tid < 3) b3s[tid] = b3g[tid];
  __syncthreads();

  float acc[2][8][4];

  // non-gather feature for global column k, row r (0 for padding)
  auto feat = [&](int k, int r) -> float {
    if (!TRIP){
      int b = k - 256;
      if ((unsigned)b < 100u){ float d = mus[b] - rns[r]; return __expf(-10.0f * d * d); }
      return 0.0f;
    } else {
      if (k < 484){
        int b = k - 384;
        if (b >= 0 && b < 100){ float d = mus[b] - rns[r]; return __expf(-10.0f * d * d); }
        return 0.0f;
      } else if (k < 584){
        float d = mus[k - 484] - rns[128 + r];
        return __expf(-10.0f * d * d);
      } else if (k == 584) return css[r];
      else if (k == 585)   return sss[r];
      return 0.0f;
    }
  };

  // build layer-0 chunk c (128 rows x 64 k-cols), hi/lo split, 128B rows, 8-slot swizzle
  auto genchunk = [&](int c, int slot){
    const int r  = tid & 127;
    const int gb = (tid >> 7) * 2;        // first of two 8-col groups: 0,2,4,6
    const int k0 = c * 64;
    unsigned char* hb = sm + X0_OFF + slot * 32768;
    #pragma unroll
    for (int g = 0; g < 2; g++){
      const int kk = k0 + (gb + g) * 8;
      float4 f0, f1;
      if (k0 < KGATH){
        const float* src = h + (size_t)idxs[(kk >> 7) * 128 + r] * 128 + (kk & 127);
        f0 = *(const float4*)src;
        f1 = *(const float4*)(src + 4);
      } else {
        f0.x = feat(kk,   r); f0.y = feat(kk+1, r); f0.z = feat(kk+2, r); f0.w = feat(kk+3, r);
        f1.x = feat(kk+4, r); f1.y = feat(kk+5, r); f1.z = feat(kk+6, r); f1.w = feat(kk+7, r);
      }
      uint4 hv, lv;
      split2(f0.x, f0.y, hv.x, lv.x);
      split2(f0.z, f0.w, hv.y, lv.y);
      split2(f1.x, f1.y, hv.z, lv.z);
      split2(f1.z, f1.w, hv.w, lv.w);
      const uint32_t off = (uint32_t)(r * 128 + ((((unsigned)(gb + g)) ^ (unsigned)(r & 7)) << 4));
      *(uint4*)(hb + off)         = hv;
      *(uint4*)(hb + 16384 + off) = lv;
    }
  };

  auto stageW = [&](const unsigned short* wbase, int j){
    const char* s = (const char*)wbase + (size_t)j * 16384 + tid * 16;
    uint32_t d = sb + W_BUF + (uint32_t)((j % 3) * 16384) + tid * 16;
    cp16s(d, s);
    cp16s(d + 8192, s + 8192);
    cp_commit();
  };

  // one layer: stream W units [c0 hi, c0 lo, ...]; per unit: hi -> (Ahi,Alo), lo -> (Ahi)
  auto run_layer = [&](int nu, const unsigned short* wbase, bool isL0){
    #pragma unroll
    for (int t = 0; t < 2; t++)
      #pragma unroll
      for (int j = 0; j < 8; j++)
        #pragma unroll
        for (int q = 0; q < 4; q++) acc[t][j][q] = 0.0f;
    stageW(wbase, 0);
    stageW(wbase, 1);
    for (int j = 0; j < nu; j++){
      if (j + 1 < nu) cp_wait<1>(); else cp_wait<0>();
      __syncthreads();
      const int c32 = j >> 1;
      const uint32_t wB = sb + W_BUF + (uint32_t)((j % 3) * 16384);
      if (isL0){
        const int chunk64 = c32 >> 1;
        const uint32_t xb = sb + X0_OFF + (uint32_t)((chunk64 & 1) * 32768);
        const int kub = (c32 & 1) * 4;
        if (!(j & 1)){
          pass_k32(acc, xb,         128, kub, wB, lane, wn, m15);
          pass_k32(acc, xb + 16384, 128, kub, wB, lane, wn, m15);
        } else {
          pass_k32(acc, xb,         128, kub, wB, lane, wn, m15);
          if ((j & 3) == 1 && chunk64 + 1 < (nu >> 2))
            genchunk(chunk64 + 1, (chunk64 + 1) & 1);
        }
      } else {
        if (!(j & 1)){
          pass_k32(acc, sb + ACT_HI, 512, c32 * 4, wB, lane, wn, m15);
          pass_k32(acc, sb + ACT_LO, 512, c32 * 4, wB, lane, wn, m15);
        } else {
          pass_k32(acc, sb + ACT_HI, 512, c32 * 4, wB, lane, wn, m15);
        }
      }
      if (j + 2 < nu) stageW(wbase, j + 2);
    }
  };

  // epilogue: silu(acc) -> hi/lo bf16 into ACT (512B rows, swizzled)
  auto epi_act = [&](){
    #pragma unroll
    for (int t = 0; t < 2; t++){
      #pragma unroll
      for (int j = 0; j < 8; j++){
        const int r  = wm*32 + t*16 + (lane >> 2);
        const int cc = wn*64 + j*8 + (lane & 3) * 2;
        float s0 = silu_f(acc[t][j][0]);
        float s1 = silu_f(acc[t][j][1]);
        float s2 = silu_f(acc[t][j][2]);
        float s3 = silu_f(acc[t][j][3]);
        uint32_t hv, lv;
        const uint32_t coff = (uint32_t)(((((unsigned)(cc >> 3)) ^ (unsigned)(r & 7)) << 4) + (cc & 7) * 2);
        split2(s0, s1, hv, lv);
        *(uint32_t*)(sm + ACT_HI + r * 512 + coff) = hv;
        *(uint32_t*)(sm + ACT_LO + r * 512 + coff) = lv;
        const int r2 = r + 8;
        const uint32_t coff2 = (uint32_t)(((((unsigned)(cc >> 3)) ^ (unsigned)(r2 & 7)) << 4) + (cc & 7) * 2);
        split2(s2, s3, hv, lv);
        *(uint32_t*)(sm + ACT_HI + r2 * 512 + coff2) = hv;
        *(uint32_t*)(sm + ACT_LO + r2 * 512 + coff2) = lv;
      }
    }
  };

  // ---- layer 0 ----
  genchunk(0, 0);
  run_layer(2 * NCH0, wimg, true);
  __syncthreads();
  epi_act();
  __syncthreads();
  // ---- layer 1 ----
  run_layer(16, wimg + (size_t)(2 * NCH0) * 8192, false);
  __syncthreads();
  epi_act();
  __syncthreads();
  // ---- layer 2 ----
  run_layer(16, wimg + (size_t)(2 * NCH0 + 16) * 8192, false);
  __syncthreads();
  // epilogue: fp32 silu into stride-257 buffer (conflict-free for layer 3)
  {
    float* actf = (float*)(sm + ACT_HI);
    #pragma unroll
    for (int t = 0; t < 2; t++){
      #pragma unroll
      for (int j = 0; j < 8; j++){
        const int r  = wm*32 + t*16 + (lane >> 2);
        const int cc = wn*64 + j*8 + (lane & 3) * 2;
        actf[r * 257 + cc]           = silu_f(acc[t][j][0]);
        actf[r * 257 + cc + 1]       = silu_f(acc[t][j][1]);
        actf[(r + 8) * 257 + cc]     = silu_f(acc[t][j][2]);
        actf[(r + 8) * 257 + cc + 1] = silu_f(acc[t][j][3]);
      }
    }
  }
  __syncthreads();
  // ---- layer 3: [128 x 256] @ W3[256 x 3] + b3 ----
  if (tid < 384){
    const float* actf = (const float*)(sm + ACT_HI);
    const int r = tid / 3, o = tid - r * 3;
    float s = b3s[o];
    #pragma unroll 8
    for (int k = 0; k < 256; k++)
      s = fmaf(actf[r * 257 + k], w3s[k * 3 + o], s);
    out[(size_t)(row0 + r) * 3 + o] = s;
  }
}

extern "C" void kernel_launch(void* const* d_in, const int* in_sizes, int n_in,
                              void* d_out, int out_size){
  const float* h     = (const float*)d_in[0];
  const int*   src   = (const int*)  d_in[1];
  const int*   dst   = (const int*)  d_in[2];
  const float* enorm = (const float*)d_in[3];
  const int*   tsrc  = (const int*)  d_in[4];
  const int*   tdi   = (const int*)  d_in[5];
  const int*   tdj   = (const int*)  d_in[6];
  const float* nij   = (const float*)d_in[7];
  const float* nik   = (const float*)d_in[8];
  const float* cosv  = (const float*)d_in[9];
  const float* sinv  = (const float*)d_in[10];
  const float* mu    = (const float*)d_in[11];
  const float* eW0   = (const float*)d_in[12];
  const float* eW1   = (const float*)d_in[13];
  const float* eW2   = (const float*)d_in[14];
  const float* eW3   = (const float*)d_in[15];
  const float* eb3   = (const float*)d_in[16];
  const float* tW0   = (const float*)d_in[17];
  const float* tW1   = (const float*)d_in[18];
  const float* tW2   = (const float*)d_in[19];
  const float* tW3   = (const float*)d_in[20];
  const float* tb3   = (const float*)d_in[21];
  float* out = (float*)d_out;

  void *pe = 0, *pt = 0;
  cudaGetSymbolAddress(&pe, g_wimg_e);
  cudaGetSymbolAddress(&pt, g_wimg_t);
  unsigned short* we = (unsigned short*)pe;
  unsigned short* wt = (unsigned short*)pt;

  // weight prep (deterministic, capturable). Triplet W0 padded 586 -> 640 (20 chunks).
  prep_w<<<(384 * 256 + 255) / 256, 256>>>(eW0, we,            356, 384);
  prep_w<<<256, 256>>>(eW1, we + (size_t)24 * 8192, 256, 256);
  prep_w<<<256, 256>>>(eW2, we + (size_t)40 * 8192, 256, 256);
  prep_w<<<(640 * 256 + 255) / 256, 256>>>(tW0, wt,            586, 640);
  prep_w<<<256, 256>>>(tW1, wt + (size_t)40 * 8192, 256, 256);
  prep_w<<<256, 256>>>(tW2, wt + (size_t)56 * 8192, 256, 256);

  cudaFuncSetAttribute(mlp_mma<false, 256, 12>, cudaFuncAttributeMaxDynamicSharedMemorySize, SMEM_TOTAL);
  cudaFuncSetAttribute(mlp_mma<true,  384, 20>, cudaFuncAttributeMaxDynamicSharedMemorySize, SMEM_TOTAL);

  mlp_mma<false, 256, 12><<<NEDGE / TILE_M, NTH, SMEM_TOTAL>>>(
      h, src, dst, dst, enorm, enorm, enorm, enorm, mu, eW3, eb3, we, out);
  mlp_mma<true, 384, 20><<<NTRI / TILE_M, NTH, SMEM_TOTAL>>>(
      h, tsrc, tdi, tdj, nij, nik, cosv, sinv, mu, tW3, tb3, wt, out + (size_t)NEDGE * 3);
}

// round 5
// speedup vs baseline: 2.6152x; 1.0303x over previous
#include <cuda_runtime.h>
#include <cuda_bf16.h>
#include <stdint.h>

#define NEDGE 262144
#define NTRI  393216
#define TILE_M 128
#define NTH   512
#define NBLK_E (NEDGE/TILE_M)   // 2048
#define NBLK_T (NTRI/TILE_M)    // 3072

// ---- smem byte offsets ----
#define W_BUF   0            // 2 pair-slots x 32768 = 65536
#define X0_OFF  65536        // 2 slots x 32768 (layer0 ring; overlaps ACT, dead after L0)
#define ACT_HI  65536        // 65536  (128 rows x 512B)
#define ACT_LO  131072       // 65536
#define MISC    197632       // fp32 act buffer (131584B from ACT_HI) ends at 197120
#define OFF_W3  (MISC)
#define OFF_B3  (MISC+3072)
#define OFF_MU  (MISC+3088)
#define OFF_IDX (MISC+3504)
#define OFF_RN  (MISC+5040)
#define OFF_CS  (MISC+6064)
#define OFF_SS  (MISC+6576)
#define SMEM_TOTAL (MISC+7168)   // 204800

// weight images: units of 32k x 256n bf16 (8192 u16 = 16KB), [c0 hi, c0 lo, c1 hi, ...]
__device__ __align__(16) unsigned short g_wimg_e[458752]; // (24+16+16) units
__device__ __align__(16) unsigned short g_wimg_t[589824]; // (40+16+16) units

__device__ __forceinline__ uint32_t smem_u32(const void* p){
  uint32_t a;
  asm("{ .reg .u64 t; cvta.to.shared.u64 t, %1; cvt.u32.u64 %0, t; }" : "=r"(a) : "l"(p));
  return a;
}
__device__ __forceinline__ void cp16s(uint32_t dst, const void* src){
  asm volatile("cp.async.cg.shared.global [%0], [%1], 16;" :: "r"(dst), "l"(src) : "memory");
}
__device__ __forceinline__ void cp_commit(){ asm volatile("cp.async.commit_group;" ::: "memory"); }
template<int N> __device__ __forceinline__ void cp_wait(){ asm volatile("cp.async.wait_group %0;" :: "n"(N) : "memory"); }

__device__ __forceinline__ void ldsm4(uint32_t (&r)[4], uint32_t a){
  asm volatile("ldmatrix.sync.aligned.m8n8.x4.shared.b16 {%0,%1,%2,%3}, [%4];"
    : "=r"(r[0]), "=r"(r[1]), "=r"(r[2]), "=r"(r[3]) : "r"(a));
}
__device__ __forceinline__ void ldsm4t(uint32_t (&r)[4], uint32_t a){
  asm volatile("ldmatrix.sync.aligned.m8n8.x4.trans.shared.b16 {%0,%1,%2,%3}, [%4];"
    : "=r"(r[0]), "=r"(r[1]), "=r"(r[2]), "=r"(r[3]) : "r"(a));
}
__device__ __forceinline__ void mma_bf(float (&d)[4], const uint32_t (&a)[4], uint32_t b0, uint32_t b1){
  asm volatile("mma.sync.aligned.m16n8k16.row.col.f32.bf16.bf16.f32 "
    "{%0,%1,%2,%3}, {%4,%5,%6,%7}, {%8,%9}, {%0,%1,%2,%3};"
    : "+f"(d[0]), "+f"(d[1]), "+f"(d[2]), "+f"(d[3])
    : "r"(a[0]), "r"(a[1]), "r"(a[2]), "r"(a[3]), "r"(b0), "r"(b1));
}

__device__ __forceinline__ uint32_t pack_bf2(float x, float y){
  __nv_bfloat162 t = __floats2bfloat162_rn(x, y);
  return *(uint32_t*)&t;
}
__device__ __forceinline__ void split2(float x, float y, uint32_t& hv, uint32_t& lv){
  __nv_bfloat16 hx = __float2bfloat16(x), hy = __float2bfloat16(y);
  float lx = x - __bfloat162float(hx), ly = y - __bfloat162float(hy);
  hv = ((uint32_t)*(unsigned short*)&hx) | (((uint32_t)*(unsigned short*)&hy) << 16);
  lv = pack_bf2(lx, ly);
}
__device__ __forceinline__ float silu_f(float x){
  return __fdividef(x, 1.0f + __expf(-x));
}

// Combined split pass over one 32-k chunk: D += Ahi*Whi + Alo*Whi + Ahi*Wlo.
// Loads each A/W fragment exactly once. Per-warp tile 32m x 64n.
__device__ __forceinline__ void pass_pair(float (&acc)[2][8][4],
    uint32_t aHi, uint32_t aLo, int aRB, int kub,
    uint32_t wHi, uint32_t wLo, int lane, int wn, int m15){
  #pragma unroll
  for (int ks = 0; ks < 2; ks++){
    const int ku = kub + ks*2 + (lane >> 4);
    const uint32_t sw = (uint32_t)((ku ^ (lane & 7)) << 4);
    const uint32_t ro = (uint32_t)(m15 * aRB);
    uint32_t ah0[4], ah1[4], al0[4], al1[4];
    ldsm4(ah0, aHi + ro + sw);
    ldsm4(ah1, aHi + ro + 16*aRB + sw);
    ldsm4(al0, aLo + ro + sw);
    ldsm4(al1, aLo + ro + 16*aRB + sw);
    const uint32_t wro = (uint32_t)((ks*16 + (lane & 15)) * 512);
    #pragma unroll
    for (int jj = 0; jj < 4; jj++){
      const int nu = wn*8 + jj*2 + (lane >> 4);
      const uint32_t nsw = (uint32_t)((nu ^ (lane & 7)) << 4);
      uint32_t bh[4], bl[4];
      ldsm4t(bh, wHi + wro + nsw);
      ldsm4t(bl, wLo + wro + nsw);
      mma_bf(acc[0][2*jj],   ah0, bh[0], bh[1]);
      mma_bf(acc[0][2*jj+1], ah0, bh[2], bh[3]);
      mma_bf(acc[1][2*jj],   ah1, bh[0], bh[1]);
      mma_bf(acc[1][2*jj+1], ah1, bh[2], bh[3]);
      mma_bf(acc[0][2*jj],   al0, bh[0], bh[1]);
      mma_bf(acc[0][2*jj+1], al0, bh[2], bh[3]);
      mma_bf(acc[1][2*jj],   al1, bh[0], bh[1]);
      mma_bf(acc[1][2*jj+1], al1, bh[2], bh[3]);
      mma_bf(acc[0][2*jj],   ah0, bl[0], bl[1]);
      mma_bf(acc[0][2*jj+1], ah0, bl[2], bl[3]);
      mma_bf(acc[1][2*jj],   ah1, bl[0], bl[1]);
      mma_bf(acc[1][2*jj+1], ah1, bl[2], bl[3]);
    }
  }
}

// ---- weight prep: all 6 matrices in one launch (blockIdx.y = job) ----
__global__ void prep_all(const float* __restrict__ eW0, const float* __restrict__ eW1,
                         const float* __restrict__ eW2, const float* __restrict__ tW0,
                         const float* __restrict__ tW1, const float* __restrict__ tW2){
  const int job = blockIdx.y;
  const float* W; unsigned short* img; int KIN, Kpad;
  switch (job){
    case 0: W = eW0; img = g_wimg_e;                     KIN = 356; Kpad = 384; break;
    case 1: W = eW1; img = g_wimg_e + (size_t)24*8192;   KIN = 256; Kpad = 256; break;
    case 2: W = eW2; img = g_wimg_e + (size_t)40*8192;   KIN = 256; Kpad = 256; break;
    case 3: W = tW0; img = g_wimg_t;                     KIN = 586; Kpad = 640; break;
    case 4: W = tW1; img = g_wimg_t + (size_t)40*8192;   KIN = 256; Kpad = 256; break;
    default:W = tW2; img = g_wimg_t + (size_t)56*8192;   KIN = 256; Kpad = 256; break;
  }
  int gid = blockIdx.x * blockDim.x + threadIdx.x;
  if (gid >= Kpad * 256) return;
  int k = gid >> 8, n = gid & 255;
  float x = (k < KIN) ? W[k * 256 + n] : 0.0f;
  __nv_bfloat16 hb = __float2bfloat16(x);
  float rem = x - __bfloat162float(hb);
  __nv_bfloat16 lb = __float2bfloat16(rem);
  int c = k >> 5, kin = k & 31;
  int idx16 = kin * 256 + (((n >> 3) ^ (kin & 7)) << 3) + (n & 7);
  img[(size_t)(2*c)     * 8192 + idx16] = *(unsigned short*)&hb;
  img[(size_t)(2*c + 1) * 8192 + idx16] = *(unsigned short*)&lb;
}

// ---------------- fused MLP body ----------------
template<bool TRIP, int KGATH, int NCH0>
__device__ __forceinline__ void mlp_body(int bid,
        const float* __restrict__ h,
        const int* __restrict__ i0, const int* __restrict__ i1, const int* __restrict__ i2,
        const float* __restrict__ rn0g, const float* __restrict__ rn1g,
        const float* __restrict__ cvg, const float* __restrict__ svg,
        const float* __restrict__ mug,
        const float* __restrict__ w3g, const float* __restrict__ b3g,
        const unsigned short* __restrict__ wimg,
        float* __restrict__ out, unsigned char* sm, uint32_t sb)
{
  const int tid = threadIdx.x, lane = tid & 31, wid = tid >> 5;
  const int wm = wid & 3, wn = wid >> 2;
  const int m15 = wm*32 + (lane & 15);
  const int row0 = bid * TILE_M;

  float* w3s = (float*)(sm + OFF_W3);
  float* b3s = (float*)(sm + OFF_B3);
  float* mus = (float*)(sm + OFF_MU);
  int*   idxs = (int*)(sm + OFF_IDX);
  float* rns = (float*)(sm + OFF_RN);
  float* css = (float*)(sm + OFF_CS);
  float* sss = (float*)(sm + OFF_SS);

  if (tid < 128){
    idxs[tid]       = i0[row0 + tid];
    idxs[128 + tid] = i1[row0 + tid];
    rns[tid]        = rn0g[row0 + tid];
    if (TRIP){
      idxs[256 + tid] = i2[row0 + tid];
      rns[128 + tid]  = rn1g[row0 + tid];
      css[tid]        = cvg[row0 + tid];
      sss[tid]        = svg[row0 + tid];
    }
  }
  if (tid < 100) mus[tid] = mug[tid];
  for (int i = tid; i < 768; i += NTH) w3s[i] = w3g[i];
  if (tid < 3) b3s[tid] = b3g[tid];
  __syncthreads();

  float acc[2][8][4];

  auto feat = [&](int k, int r) -> float {
    if (!TRIP){
      int b = k - 256;
      if ((unsigned)b < 100u){ float d = mus[b] - rns[r]; return __expf(-10.0f * d * d); }
      return 0.0f;
    } else {
      if (k < 484){
        int b = k - 384;
        if (b >= 0 && b < 100){ float d = mus[b] - rns[r]; return __expf(-10.0f * d * d); }
        return 0.0f;
      } else if (k < 584){
        float d = mus[k - 484] - rns[128 + r];
        return __expf(-10.0f * d * d);
      } else if (k == 584) return css[r];
      else if (k == 585)   return sss[r];
      return 0.0f;
    }
  };

  // build layer-0 chunk c (128 rows x 64 k-cols), hi/lo split, 128B rows, 8-slot swizzle
  auto genchunk = [&](int c, int slot){
    const int r  = tid & 127;
    const int gb = (tid >> 7) * 2;
    const int k0 = c * 64;
    unsigned char* hb = sm + X0_OFF + slot * 32768;
    #pragma unroll
    for (int g = 0; g < 2; g++){
      const int kk = k0 + (gb + g) * 8;
      float4 f0, f1;
      if (k0 < KGATH){
        const float* src = h + (size_t)idxs[(kk >> 7) * 128 + r] * 128 + (kk & 127);
        f0 = *(const float4*)src;
        f1 = *(const float4*)(src + 4);
      } else {
        f0.x = feat(kk,   r); f0.y = feat(kk+1, r); f0.z = feat(kk+2, r); f0.w = feat(kk+3, r);
        f1.x = feat(kk+4, r); f1.y = feat(kk+5, r); f1.z = feat(kk+6, r); f1.w = feat(kk+7, r);
      }
      uint4 hv, lv;
      split2(f0.x, f0.y, hv.x, lv.x);
      split2(f0.z, f0.w, hv.y, lv.y);
      split2(f1.x, f1.y, hv.z, lv.z);
      split2(f1.z, f1.w, hv.w, lv.w);
      const uint32_t off = (uint32_t)(r * 128 + ((((unsigned)(gb + g)) ^ (unsigned)(r & 7)) << 4));
      *(uint4*)(hb + off)         = hv;
      *(uint4*)(hb + 16384 + off) = lv;
    }
  };

  // stage one 32KB (hi,lo) pair: 64B per thread
  auto stagePair = [&](const unsigned short* wbase, int p){
    const char* s = (const char*)wbase + (size_t)p * 32768 + tid * 16;
    uint32_t d = sb + W_BUF + (uint32_t)((p & 1) * 32768) + tid * 16;
    #pragma unroll
    for (int i = 0; i < 4; i++) cp16s(d + i * 8192, s + i * 8192);
    cp_commit();
  };

  auto run_layer = [&](int npair, const unsigned short* wbase, bool isL0){
    #pragma unroll
    for (int t = 0; t < 2; t++)
      #pragma unroll
      for (int j = 0; j < 8; j++)
        #pragma unroll
        for (int q = 0; q < 4; q++) acc[t][j][q] = 0.0f;
    stagePair(wbase, 0);
    stagePair(wbase, 1);
    for (int p = 0; p < npair; p++){
      if (p + 1 < npair) cp_wait<1>(); else cp_wait<0>();
      __syncthreads();
      if (isL0 && (p & 1) && ((p >> 1) + 1 < (npair >> 1)))
        genchunk((p >> 1) + 1, ((p >> 1) + 1) & 1);
      const uint32_t wH = sb + W_BUF + (uint32_t)((p & 1) * 32768);
      if (isL0){
        const uint32_t xb = sb + X0_OFF + (uint32_t)(((p >> 1) & 1) * 32768);
        pass_pair(acc, xb, xb + 16384, 128, (p & 1) * 4, wH, wH + 16384, lane, wn, m15);
      } else {
        pass_pair(acc, sb + ACT_HI, sb + ACT_LO, 512, p * 4, wH, wH + 16384, lane, wn, m15);
      }
      __syncthreads();
      if (p + 2 < npair) stagePair(wbase, p + 2);
    }
  };

  auto epi_act = [&](){
    #pragma unroll
    for (int t = 0; t < 2; t++){
      #pragma unroll
      for (int j = 0; j < 8; j++){
        const int r  = wm*32 + t*16 + (lane >> 2);
        const int cc = wn*64 + j*8 + (lane & 3) * 2;
        float s0 = silu_f(acc[t][j][0]);
        float s1 = silu_f(acc[t][j][1]);
        float s2 = silu_f(acc[t][j][2]);
        float s3 = silu_f(acc[t][j][3]);
        uint32_t hv, lv;
        const uint32_t coff = (uint32_t)(((((unsigned)(cc >> 3)) ^ (unsigned)(r & 7)) << 4) + (cc & 7) * 2);
        split2(s0, s1, hv, lv);
        *(uint32_t*)(sm + ACT_HI + r * 512 + coff) = hv;
        *(uint32_t*)(sm + ACT_LO + r * 512 + coff) = lv;
        const int r2 = r + 8;
        const uint32_t coff2 = (uint32_t)(((((unsigned)(cc >> 3)) ^ (unsigned)(r2 & 7)) << 4) + (cc & 7) * 2);
        split2(s2, s3, hv, lv);
        *(uint32_t*)(sm + ACT_HI + r2 * 512 + coff2) = hv;
        *(uint32_t*)(sm + ACT_LO + r2 * 512 + coff2) = lv;
      }
    }
  };

  // ---- layer 0 ----
  genchunk(0, 0);
  run_layer(NCH0, wimg, true);
  epi_act();
  __syncthreads();
  // ---- layer 1 ----
  run_layer(8, wimg + (size_t)(2 * NCH0) * 8192, false);
  epi_act();
  __syncthreads();
  // ---- layer 2 ----
  run_layer(8, wimg + (size_t)(2 * NCH0 + 16) * 8192, false);
  // fp32 silu into stride-257 buffer
  {
    float* actf = (float*)(sm + ACT_HI);
    #pragma unroll
    for (int t = 0; t < 2; t++){
      #pragma unroll
      for (int j = 0; j < 8; j++){
        const int r  = wm*32 + t*16 + (lane >> 2);
        const int cc = wn*64 + j*8 + (lane & 3) * 2;
        actf[r * 257 + cc]           = silu_f(acc[t][j][0]);
        actf[r * 257 + cc + 1]       = silu_f(acc[t][j][1]);
        actf[(r + 8) * 257 + cc]     = silu_f(acc[t][j][2]);
        actf[(r + 8) * 257 + cc + 1] = silu_f(acc[t][j][3]);
      }
    }
  }
  __syncthreads();
  // ---- layer 3 ----
  if (tid < 384){
    const float* actf = (const float*)(sm + ACT_HI);
    const int r = tid / 3, o = tid - r * 3;
    float s = b3s[o];
    #pragma unroll 8
    for (int k = 0; k < 256; k++)
      s = fmaf(actf[r * 257 + k], w3s[k * 3 + o], s);
    out[(size_t)(row0 + r) * 3 + o] = s;
  }
}

__global__ void __launch_bounds__(NTH, 1)
mlp_all(const float* __restrict__ h,
        const int* __restrict__ src, const int* __restrict__ dst,
        const float* __restrict__ enorm,
        const int* __restrict__ tsrc, const int* __restrict__ tdi, const int* __restrict__ tdj,
        const float* __restrict__ nij, const float* __restrict__ nik,
        const float* __restrict__ cosv, const float* __restrict__ sinv,
        const float* __restrict__ mu,
        const float* __restrict__ eW3, const float* __restrict__ eb3,
        const float* __restrict__ tW3, const float* __restrict__ tb3,
        float* __restrict__ out)
{
  extern __shared__ __align__(1024) unsigned char sm[];
  const uint32_t sb = smem_u32(sm);
  const int bid = blockIdx.x;
  if (bid < NBLK_E){
    mlp_body<false, 256, 12>(bid, h, src, dst, dst, enorm, enorm, enorm, enorm, mu,
                             eW3, eb3, (const unsigned short*)g_wimg_e, out, sm, sb);
  } else {
    mlp_body<true, 384, 20>(bid - NBLK_E, h, tsrc, tdi, tdj, nij, nik, cosv, sinv, mu,
                            tW3, tb3, (const unsigned short*)g_wimg_t,
                            out + (size_t)NEDGE * 3, sm, sb);
  }
}

extern "C" void kernel_launch(void* const* d_in, const int* in_sizes, int n_in,
                              void* d_out, int out_size){
  const float* h     = (const float*)d_in[0];
  const int*   src   = (const int*)  d_in[1];
  const int*   dst   = (const int*)  d_in[2];
  const float* enorm = (const float*)d_in[3];
  const int*   tsrc  = (const int*)  d_in[4];
  const int*   tdi   = (const int*)  d_in[5];
  const int*   tdj   = (const int*)  d_in[6];
  const float* nij   = (const float*)d_in[7];
  const float* nik   = (const float*)d_in[8];
  const float* cosv  = (const float*)d_in[9];
  const float* sinv  = (const float*)d_in[10];
  const float* mu    = (const float*)d_in[11];
  const float* eW0   = (const float*)d_in[12];
  const float* eW1   = (const float*)d_in[13];
  const float* eW2   = (const float*)d_in[14];
  const float* eW3   = (const float*)d_in[15];
  const float* eb3   = (const float*)d_in[16];
  const float* tW0   = (const float*)d_in[17];
  const float* tW1   = (const float*)d_in[18];
  const float* tW2   = (const float*)d_in[19];
  const float* tW3   = (const float*)d_in[20];
  const float* tb3   = (const float*)d_in[21];
  float* out = (float*)d_out;

  prep_all<<<dim3(640, 6), 256>>>(eW0, eW1, eW2, tW0, tW1, tW2);

  cudaFuncSetAttribute(mlp_all, cudaFuncAttributeMaxDynamicSharedMemorySize, SMEM_TOTAL);
  mlp_all<<<NBLK_E + NBLK_T, NTH, SMEM_TOTAL>>>(
      h, src, dst, enorm, tsrc, tdi, tdj, nij, nik, cosv, sinv, mu,
      eW3, eb3, tW3, tb3, out);
}

// round 6
// speedup vs baseline: 3.6337x; 1.3894x over previous
#include <cuda_runtime.h>
#include <cuda_fp16.h>
#include <stdint.h>

#define NEDGE 262144
#define NTRI  393216
#define TILE_M 128
#define NTH   512
#define NBLK_E (NEDGE/TILE_M)   // 2048
#define NBLK_T (NTRI/TILE_M)    // 3072

// ---- smem byte offsets ----
#define W_BUF   0            // 4 pair-slots x 32768 = 131072
#define ACT16   131072       // 65536 (128 rows x 512B fp16)
#define X0_OFF  131072       // 2 slots x 16384 (layer0 ring; overlaps ACT, dead after L0)
#define F32BUF  0            // layer-3 fp32 act, 131584B (overlaps W ring, used after L2)
#define MISC    196608
#define OFF_W3  (MISC)
#define OFF_B3  (MISC+3072)
#define OFF_MU  (MISC+3088)
#define OFF_IDX (MISC+3504)
#define OFF_RN  (MISC+5040)
#define OFF_CS  (MISC+6064)
#define OFF_SS  (MISC+6576)
#define SMEM_TOTAL (MISC+7168)   // 203776

// weight images: units of 32k x 256n fp16 (8192 u16 = 16KB), [c0 hi, c0 lo, c1 hi, ...]
__device__ __align__(16) unsigned short g_wimg_e[458752]; // (24+16+16) units
__device__ __align__(16) unsigned short g_wimg_t[589824]; // (40+16+16) units

__device__ __forceinline__ uint32_t smem_u32(const void* p){
  uint32_t a;
  asm("{ .reg .u64 t; cvta.to.shared.u64 t, %1; cvt.u32.u64 %0, t; }" : "=r"(a) : "l"(p));
  return a;
}
__device__ __forceinline__ void cp16s(uint32_t dst, const void* src){
  asm volatile("cp.async.cg.shared.global [%0], [%1], 16;" :: "r"(dst), "l"(src) : "memory");
}
__device__ __forceinline__ void cp_commit(){ asm volatile("cp.async.commit_group;" ::: "memory"); }
template<int N> __device__ __forceinline__ void cp_wait(){ asm volatile("cp.async.wait_group %0;" :: "n"(N) : "memory"); }

__device__ __forceinline__ void ldsm4(uint32_t (&r)[4], uint32_t a){
  asm volatile("ldmatrix.sync.aligned.m8n8.x4.shared.b16 {%0,%1,%2,%3}, [%4];"
    : "=r"(r[0]), "=r"(r[1]), "=r"(r[2]), "=r"(r[3]) : "r"(a));
}
__device__ __forceinline__ void ldsm4t(uint32_t (&r)[4], uint32_t a){
  asm volatile("ldmatrix.sync.aligned.m8n8.x4.trans.shared.b16 {%0,%1,%2,%3}, [%4];"
    : "=r"(r[0]), "=r"(r[1]), "=r"(r[2]), "=r"(r[3]) : "r"(a));
}
__device__ __forceinline__ void mma_fp(float (&d)[4], const uint32_t (&a)[4], uint32_t b0, uint32_t b1){
  asm volatile("mma.sync.aligned.m16n8k16.row.col.f32.f16.f16.f32 "
    "{%0,%1,%2,%3}, {%4,%5,%6,%7}, {%8,%9}, {%0,%1,%2,%3};"
    : "+f"(d[0]), "+f"(d[1]), "+f"(d[2]), "+f"(d[3])
    : "r"(a[0]), "r"(a[1]), "r"(a[2]), "r"(a[3]), "r"(b0), "r"(b1));
}

__device__ __forceinline__ uint32_t pack_h2(float x, float y){
  __half2 t = __floats2half2_rn(x, y);
  return *(uint32_t*)&t;
}
__device__ __forceinline__ float silu_f(float x){
  return __fdividef(x, 1.0f + __expf(-x));
}

// 2-pass over one 32-k chunk: D += A*Whi + A*Wlo (A fp16, W split fp16 = 22-bit W)
// Per-warp tile 32m x 64n. 20 LDSM, 64 HMMA per chunk.
__device__ __forceinline__ void pass_chunk(float (&acc)[2][8][4],
    uint32_t aB, int aRB, int kub,
    uint32_t wHi, uint32_t wLo, int lane, int wn, int m15){
  #pragma unroll
  for (int ks = 0; ks < 2; ks++){
    const int ku = kub + ks*2 + (lane >> 4);
    const uint32_t sw = (uint32_t)((ku ^ (lane & 7)) << 4);
    const uint32_t ro = (uint32_t)(m15 * aRB);
    uint32_t a0[4], a1[4];
    ldsm4(a0, aB + ro + sw);
    ldsm4(a1, aB + ro + 16*aRB + sw);
    const uint32_t wro = (uint32_t)((ks*16 + (lane & 15)) * 512);
    #pragma unroll
    for (int jj = 0; jj < 4; jj++){
      const int nu = wn*8 + jj*2 + (lane >> 4);
      const uint32_t nsw = (uint32_t)((nu ^ (lane & 7)) << 4);
      uint32_t bh[4], bl[4];
      ldsm4t(bh, wHi + wro + nsw);
      ldsm4t(bl, wLo + wro + nsw);
      mma_fp(acc[0][2*jj],   a0, bh[0], bh[1]);
      mma_fp(acc[0][2*jj+1], a0, bh[2], bh[3]);
      mma_fp(acc[1][2*jj],   a1, bh[0], bh[1]);
      mma_fp(acc[1][2*jj+1], a1, bh[2], bh[3]);
      mma_fp(acc[0][2*jj],   a0, bl[0], bl[1]);
      mma_fp(acc[0][2*jj+1], a0, bl[2], bl[3]);
      mma_fp(acc[1][2*jj],   a1, bl[0], bl[1]);
      mma_fp(acc[1][2*jj+1], a1, bl[2], bl[3]);
    }
  }
}

// ---- weight prep: all 6 matrices, fp16 hi/lo, pre-swizzled units ----
__global__ void prep_all(const float* __restrict__ eW0, const float* __restrict__ eW1,
                         const float* __restrict__ eW2, const float* __restrict__ tW0,
                         const float* __restrict__ tW1, const float* __restrict__ tW2){
  const int job = blockIdx.y;
  const float* W; unsigned short* img; int KIN, Kpad;
  switch (job){
    case 0: W = eW0; img = g_wimg_e;                     KIN = 356; Kpad = 384; break;
    case 1: W = eW1; img = g_wimg_e + (size_t)24*8192;   KIN = 256; Kpad = 256; break;
    case 2: W = eW2; img = g_wimg_e + (size_t)40*8192;   KIN = 256; Kpad = 256; break;
    case 3: W = tW0; img = g_wimg_t;                     KIN = 586; Kpad = 640; break;
    case 4: W = tW1; img = g_wimg_t + (size_t)40*8192;   KIN = 256; Kpad = 256; break;
    default:W = tW2; img = g_wimg_t + (size_t)56*8192;   KIN = 256; Kpad = 256; break;
  }
  int gid = blockIdx.x * blockDim.x + threadIdx.x;
  if (gid >= Kpad * 256) return;
  int k = gid >> 8, n = gid & 255;
  float x = (k < KIN) ? W[k * 256 + n] : 0.0f;
  __half hb = __float2half_rn(x);
  float rem = x - __half2float(hb);
  __half lb = __float2half_rn(rem);
  int c = k >> 5, kin = k & 31;
  int idx16 = kin * 256 + (((n >> 3) ^ (kin & 7)) << 3) + (n & 7);
  img[(size_t)(2*c)     * 8192 + idx16] = *(unsigned short*)&hb;
  img[(size_t)(2*c + 1) * 8192 + idx16] = *(unsigned short*)&lb;
}

// ---------------- fused MLP body ----------------
template<bool TRIP, int KGATH, int NCH0>
__device__ __forceinline__ void mlp_body(int bid,
        const float* __restrict__ h,
        const int* __restrict__ i0, const int* __restrict__ i1, const int* __restrict__ i2,
        const float* __restrict__ rn0g, const float* __restrict__ rn1g,
        const float* __restrict__ cvg, const float* __restrict__ svg,
        const float* __restrict__ mug,
        const float* __restrict__ w3g, const float* __restrict__ b3g,
        const unsigned short* __restrict__ wimg,
        float* __restrict__ out, unsigned char* sm, uint32_t sb)
{
  const int tid = threadIdx.x, lane = tid & 31, wid = tid >> 5;
  const int wm = wid & 3, wn = wid >> 2;
  const int m15 = wm*32 + (lane & 15);
  const int row0 = bid * TILE_M;

  float* w3s = (float*)(sm + OFF_W3);
  float* b3s = (float*)(sm + OFF_B3);
  float* mus = (float*)(sm + OFF_MU);
  int*   idxs = (int*)(sm + OFF_IDX);
  float* rns = (float*)(sm + OFF_RN);
  float* css = (float*)(sm + OFF_CS);
  float* sss = (float*)(sm + OFF_SS);

  if (tid < 128){
    idxs[tid]       = i0[row0 + tid];
    idxs[128 + tid] = i1[row0 + tid];
    rns[tid]        = rn0g[row0 + tid];
    if (TRIP){
      idxs[256 + tid] = i2[row0 + tid];
      rns[128 + tid]  = rn1g[row0 + tid];
      css[tid]        = cvg[row0 + tid];
      sss[tid]        = svg[row0 + tid];
    }
  }
  if (tid < 100) mus[tid] = mug[tid];
  for (int i = tid; i < 768; i += NTH) w3s[i] = w3g[i];
  if (tid < 3) b3s[tid] = b3g[tid];
  __syncthreads();

  float acc[2][8][4];

  auto feat = [&](int k, int r) -> float {
    if (!TRIP){
      int b = k - 256;
      if ((unsigned)b < 100u){ float d = mus[b] - rns[r]; return __expf(-10.0f * d * d); }
      return 0.0f;
    } else {
      if (k < 484){
        int b = k - 384;
        if (b >= 0 && b < 100){ float d = mus[b] - rns[r]; return __expf(-10.0f * d * d); }
        return 0.0f;
      } else if (k < 584){
        float d = mus[k - 484] - rns[128 + r];
        return __expf(-10.0f * d * d);
      } else if (k == 584) return css[r];
      else if (k == 585)   return sss[r];
      return 0.0f;
    }
  };

  // build layer-0 chunk c (128 rows x 64 k-cols fp16), 128B rows, 8-unit swizzle
  auto genchunk = [&](int c, int slot){
    const int r  = tid & 127;
    const int gb = (tid >> 7) * 2;
    const int k0 = c * 64;
    unsigned char* hb = sm + X0_OFF + slot * 16384;
    #pragma unroll
    for (int g = 0; g < 2; g++){
      const int u = gb + g;
      const int kk = k0 + u * 8;
      float4 f0, f1;
      if (k0 < KGATH){
        const float* src = h + (size_t)idxs[(kk >> 7) * 128 + r] * 128 + (kk & 127);
        f0 = *(const float4*)src;
        f1 = *(const float4*)(src + 4);
      } else {
        f0.x = feat(kk,   r); f0.y = feat(kk+1, r); f0.z = feat(kk+2, r); f0.w = feat(kk+3, r);
        f1.x = feat(kk+4, r); f1.y = feat(kk+5, r); f1.z = feat(kk+6, r); f1.w = feat(kk+7, r);
      }
      uint4 v;
      v.x = pack_h2(f0.x, f0.y);
      v.y = pack_h2(f0.z, f0.w);
      v.z = pack_h2(f1.x, f1.y);
      v.w = pack_h2(f1.z, f1.w);
      const uint32_t off = (uint32_t)(r * 128 + ((((unsigned)u) ^ (unsigned)(r & 7)) << 4));
      *(uint4*)(hb + off) = v;
    }
  };

  // stage one 32KB (Whi,Wlo) pair into ring slot p&3
  auto stagePair = [&](const unsigned short* wbase, int p){
    const char* s = (const char*)wbase + (size_t)p * 32768 + tid * 16;
    uint32_t d = sb + W_BUF + (uint32_t)((p & 3) * 32768) + tid * 16;
    #pragma unroll
    for (int i = 0; i < 4; i++) cp16s(d + i * 8192, s + i * 8192);
    cp_commit();
  };

  // stream npair 32-k chunks; single barrier per chunk; 4-deep ring (3 in flight)
  auto run_layer = [&](int npair, const unsigned short* wbase, bool isL0){
    #pragma unroll
    for (int t = 0; t < 2; t++)
      #pragma unroll
      for (int j = 0; j < 8; j++)
        #pragma unroll
        for (int q = 0; q < 4; q++) acc[t][j][q] = 0.0f;
    stagePair(wbase, 0);
    stagePair(wbase, 1);
    stagePair(wbase, 2);
    for (int p = 0; p < npair; p++){
      if (p <= npair - 3)      cp_wait<2>();
      else if (p == npair - 2) cp_wait<1>();
      else                     cp_wait<0>();
      __syncthreads();
      if (p + 3 < npair) stagePair(wbase, p + 3);
      if (isL0 && (p & 1) && ((p >> 1) + 1 < (npair >> 1)))
        genchunk((p >> 1) + 1, ((p >> 1) + 1) & 1);
      const uint32_t wH = sb + W_BUF + (uint32_t)((p & 3) * 32768);
      if (isL0){
        const uint32_t xb = sb + X0_OFF + (uint32_t)(((p >> 1) & 1) * 16384);
        pass_chunk(acc, xb, 128, (p & 1) * 4, wH, wH + 16384, lane, wn, m15);
      } else {
        pass_chunk(acc, sb + ACT16, 512, p * 4, wH, wH + 16384, lane, wn, m15);
      }
    }
  };

  // epilogue: silu(acc) -> fp16 ACT (512B rows, swizzled)
  auto epi_act = [&](){
    #pragma unroll
    for (int t = 0; t < 2; t++){
      #pragma unroll
      for (int j = 0; j < 8; j++){
        const int r  = wm*32 + t*16 + (lane >> 2);
        const int cc = wn*64 + j*8 + (lane & 3) * 2;
        float s0 = silu_f(acc[t][j][0]);
        float s1 = silu_f(acc[t][j][1]);
        float s2 = silu_f(acc[t][j][2]);
        float s3 = silu_f(acc[t][j][3]);
        const uint32_t coff = (uint32_t)(((((unsigned)(cc >> 3)) ^ (unsigned)(r & 7)) << 4) + (cc & 7) * 2);
        *(uint32_t*)(sm + ACT16 + r * 512 + coff) = pack_h2(s0, s1);
        const int r2 = r + 8;
        const uint32_t coff2 = (uint32_t)(((((unsigned)(cc >> 3)) ^ (unsigned)(r2 & 7)) << 4) + (cc & 7) * 2);
        *(uint32_t*)(sm + ACT16 + r2 * 512 + coff2) = pack_h2(s2, s3);
      }
    }
  };

  // ---- layer 0 ----
  genchunk(0, 0);
  run_layer(NCH0, wimg, true);
  __syncthreads();            // X0 reads done before ACT overwrite
  epi_act();
  __syncthreads();
  // ---- layer 1 ----
  run_layer(8, wimg + (size_t)(2 * NCH0) * 8192, false);
  __syncthreads();            // ACT reads done before overwrite
  epi_act();
  __syncthreads();
  // ---- layer 2 ----
  run_layer(8, wimg + (size_t)(2 * NCH0 + 16) * 8192, false);
  __syncthreads();            // W-ring reads done before F32BUF overwrite
  {
    float* actf = (float*)(sm + F32BUF);
    #pragma unroll
    for (int t = 0; t < 2; t++){
      #pragma unroll
      for (int j = 0; j < 8; j++){
        const int r  = wm*32 + t*16 + (lane >> 2);
        const int cc = wn*64 + j*8 + (lane & 3) * 2;
        actf[r * 257 + cc]           = silu_f(acc[t][j][0]);
        actf[r * 257 + cc + 1]       = silu_f(acc[t][j][1]);
        actf[(r + 8) * 257 + cc]     = silu_f(acc[t][j][2]);
        actf[(r + 8) * 257 + cc + 1] = silu_f(acc[t][j][3]);
      }
    }
  }
  __syncthreads();
  // ---- layer 3: [128 x 256] @ W3[256 x 3] + b3 ----
  if (tid < 384){
    const float* actf = (const float*)(sm + F32BUF);
    const int r = tid / 3, o = tid - r * 3;
    float s = b3s[o];
    #pragma unroll 8
    for (int k = 0; k < 256; k++)
      s = fmaf(actf[r * 257 + k], w3s[k * 3 + o], s);
    out[(size_t)(row0 + r) * 3 + o] = s;
  }
}

__global__ void __launch_bounds__(NTH, 1)
mlp_all(const float* __restrict__ h,
        const int* __restrict__ src, const int* __restrict__ dst,
        const float* __restrict__ enorm,
        const int* __restrict__ tsrc, const int* __restrict__ tdi, const int* __restrict__ tdj,
        const float* __restrict__ nij, const float* __restrict__ nik,
        const float* __restrict__ cosv, const float* __restrict__ sinv,
        const float* __restrict__ mu,
        const float* __restrict__ eW3, const float* __restrict__ eb3,
        const float* __restrict__ tW3, const float* __restrict__ tb3,
        float* __restrict__ out)
{
  extern __shared__ __align__(1024) unsigned char sm[];
  const uint32_t sb = smem_u32(sm);
  const int bid = blockIdx.x;
  if (bid < NBLK_E){
    mlp_body<false, 256, 12>(bid, h, src, dst, dst, enorm, enorm, enorm, enorm, mu,
                             eW3, eb3, (const unsigned short*)g_wimg_e, out, sm, sb);
  } else {
    mlp_body<true, 384, 20>(bid - NBLK_E, h, tsrc, tdi, tdj, nij, nik, cosv, sinv, mu,
                            tW3, tb3, (const unsigned short*)g_wimg_t,
                            out + (size_t)NEDGE * 3, sm, sb);
  }
}

extern "C" void kernel_launch(void* const* d_in, const int* in_sizes, int n_in,
                              void* d_out, int out_size){
  const float* h     = (const float*)d_in[0];
  const int*   src   = (const int*)  d_in[1];
  const int*   dst   = (const int*)  d_in[2];
  const float* enorm = (const float*)d_in[3];
  const int*   tsrc  = (const int*)  d_in[4];
  const int*   tdi   = (const int*)  d_in[5];
  const int*   tdj   = (const int*)  d_in[6];
  const float* nij   = (const float*)d_in[7];
  const float* nik   = (const float*)d_in[8];
  const float* cosv  = (const float*)d_in[9];
  const float* sinv  = (const float*)d_in[10];
  const float* mu    = (const float*)d_in[11];
  const float* eW0   = (const float*)d_in[12];
  const float* eW1   = (const float*)d_in[13];
  const float* eW2   = (const float*)d_in[14];
  const float* eW3   = (const float*)d_in[15];
  const float* eb3   = (const float*)d_in[16];
  const float* tW0   = (const float*)d_in[17];
  const float* tW1   = (const float*)d_in[18];
  const float* tW2   = (const float*)d_in[19];
  const float* tW3   = (const float*)d_in[20];
  const float* tb3   = (const float*)d_in[21];
  float* out = (float*)d_out;

  prep_all<<<dim3(640, 6), 256>>>(eW0, eW1, eW2, tW0, tW1, tW2);

  cudaFuncSetAttribute(mlp_all, cudaFuncAttributeMaxDynamicSharedMemorySize, SMEM_TOTAL);
  mlp_all<<<NBLK_E + NBLK_T, NTH, SMEM_TOTAL>>>(
      h, src, dst, enorm, tsrc, tdi, tdj, nij, nik, cosv, sinv, mu,
      eW3, eb3, tW3, tb3, out);
}

// round 7
// speedup vs baseline: 4.6210x; 1.2717x over previous
#include <cuda_runtime.h>
#include <cuda_fp16.h>
#include <stdint.h>

#define NEDGE 262144
#define NTRI  393216
#define TILE_M 128
#define NTH   512
#define NBLK_E (NEDGE/TILE_M)   // 2048
#define NBLK_T (NTRI/TILE_M)    // 3072

// ---- smem byte offsets ----
#define W_BUF   0            // 4 slots x 16384 = 65536
#define ACT16   65536        // 65536 (128 rows x 512B fp16)
#define X0_OFF  65536        // 2 slots x 16384 (layer0 ring; overlaps ACT, dead after L0)
#define F32BUF  65536        // layer-3 fp32 act 131584B (overlaps ACT16+, used after L2)
#define PARTS   0            // L3 partials 6144B (overlaps W ring, dead after L2)
#define MISC    197632
#define OFF_W3  (MISC)
#define OFF_B3  (MISC+3072)
#define OFF_MU  (MISC+3088)
#define OFF_IDX (MISC+3504)
#define OFF_RN  (MISC+5040)
#define OFF_CS  (MISC+6064)
#define OFF_SS  (MISC+6576)
#define SMEM_TOTAL (MISC+7168)   // 204800

// weight images: units of 32k x 256n fp16 (8192 u16 = 16KB), one unit per 32-k chunk.
// edges: L0 12 units @0, L1 8 @12, L2 8 @20.  trip: L0 20 @0, L1 8 @20, L2 8 @28.
__device__ __align__(16) unsigned short g_wimg_e[229376]; // 28 units
__device__ __align__(16) unsigned short g_wimg_t[294912]; // 36 units

__device__ __forceinline__ uint32_t smem_u32(const void* p){
  uint32_t a;
  asm("{ .reg .u64 t; cvta.to.shared.u64 t, %1; cvt.u32.u64 %0, t; }" : "=r"(a) : "l"(p));
  return a;
}
__device__ __forceinline__ void cp16s(uint32_t dst, const void* src){
  asm volatile("cp.async.cg.shared.global [%0], [%1], 16;" :: "r"(dst), "l"(src) : "memory");
}
__device__ __forceinline__ void cp_commit(){ asm volatile("cp.async.commit_group;" ::: "memory"); }
template<int N> __device__ __forceinline__ void cp_wait(){ asm volatile("cp.async.wait_group %0;" :: "n"(N) : "memory"); }

__device__ __forceinline__ void ldsm4(uint32_t (&r)[4], uint32_t a){
  asm volatile("ldmatrix.sync.aligned.m8n8.x4.shared.b16 {%0,%1,%2,%3}, [%4];"
    : "=r"(r[0]), "=r"(r[1]), "=r"(r[2]), "=r"(r[3]) : "r"(a));
}
__device__ __forceinline__ void ldsm4t(uint32_t (&r)[4], uint32_t a){
  asm volatile("ldmatrix.sync.aligned.m8n8.x4.trans.shared.b16 {%0,%1,%2,%3}, [%4];"
    : "=r"(r[0]), "=r"(r[1]), "=r"(r[2]), "=r"(r[3]) : "r"(a));
}
__device__ __forceinline__ void mma_fp(float (&d)[4], const uint32_t (&a)[4], uint32_t b0, uint32_t b1){
  asm volatile("mma.sync.aligned.m16n8k16.row.col.f32.f16.f16.f32 "
    "{%0,%1,%2,%3}, {%4,%5,%6,%7}, {%8,%9}, {%0,%1,%2,%3};"
    : "+f"(d[0]), "+f"(d[1]), "+f"(d[2]), "+f"(d[3])
    : "r"(a[0]), "r"(a[1]), "r"(a[2]), "r"(a[3]), "r"(b0), "r"(b1));
}

__device__ __forceinline__ uint32_t pack_h2(float x, float y){
  __half2 t = __floats2half2_rn(x, y);
  return *(uint32_t*)&t;
}
__device__ __forceinline__ float silu_f(float x){
  return __fdividef(x, 1.0f + __expf(-x));
}

// One 32-k chunk, single pass: D += A*W (fp16). 12 LDSM, 32 HMMA, warp tile 32x64.
__device__ __forceinline__ void pass_single(float (&acc)[2][8][4],
    uint32_t aB, int aRB, int kub, uint32_t wB, int lane, int wn, int m15){
  #pragma unroll
  for (int ks = 0; ks < 2; ks++){
    const int ku = kub + ks*2 + (lane >> 4);
    const uint32_t sw = (uint32_t)((ku ^ (lane & 7)) << 4);
    const uint32_t ro = (uint32_t)(m15 * aRB);
    uint32_t a0[4], a1[4];
    ldsm4(a0, aB + ro + sw);
    ldsm4(a1, aB + ro + 16*aRB + sw);
    const uint32_t wro = (uint32_t)((ks*16 + (lane & 15)) * 512);
    #pragma unroll
    for (int jj = 0; jj < 4; jj++){
      const int nu = wn*8 + jj*2 + (lane >> 4);
      const uint32_t nsw = (uint32_t)((nu ^ (lane & 7)) << 4);
      uint32_t b[4];
      ldsm4t(b, wB + wro + nsw);
      mma_fp(acc[0][2*jj],   a0, b[0], b[1]);
      mma_fp(acc[0][2*jj+1], a0, b[2], b[3]);
      mma_fp(acc[1][2*jj],   a1, b[0], b[1]);
      mma_fp(acc[1][2*jj+1], a1, b[2], b[3]);
    }
  }
}

// ---- weight prep: all 6 matrices, fp16, pre-swizzled 16KB units ----
__global__ void prep_all(const float* __restrict__ eW0, const float* __restrict__ eW1,
                         const float* __restrict__ eW2, const float* __restrict__ tW0,
                         const float* __restrict__ tW1, const float* __restrict__ tW2){
  const int job = blockIdx.y;
  const float* W; unsigned short* img; int KIN, Kpad;
  switch (job){
    case 0: W = eW0; img = g_wimg_e;                     KIN = 356; Kpad = 384; break;
    case 1: W = eW1; img = g_wimg_e + (size_t)12*8192;   KIN = 256; Kpad = 256; break;
    case 2: W = eW2; img = g_wimg_e + (size_t)20*8192;   KIN = 256; Kpad = 256; break;
    case 3: W = tW0; img = g_wimg_t;                     KIN = 586; Kpad = 640; break;
    case 4: W = tW1; img = g_wimg_t + (size_t)20*8192;   KIN = 256; Kpad = 256; break;
    default:W = tW2; img = g_wimg_t + (size_t)28*8192;   KIN = 256; Kpad = 256; break;
  }
  int gid = blockIdx.x * blockDim.x + threadIdx.x;
  if (gid >= Kpad * 256) return;
  int k = gid >> 8, n = gid & 255;
  float x = (k < KIN) ? W[k * 256 + n] : 0.0f;
  __half hb = __float2half_rn(x);
  int c = k >> 5, kin = k & 31;
  int idx16 = kin * 256 + (((n >> 3) ^ (kin & 7)) << 3) + (n & 7);
  img[(size_t)c * 8192 + idx16] = *(unsigned short*)&hb;
}

// ---------------- fused MLP body ----------------
template<bool TRIP, int KGATH, int NU0>
__device__ __forceinline__ void mlp_body(int bid,
        const float* __restrict__ h,
        const int* __restrict__ i0, const int* __restrict__ i1, const int* __restrict__ i2,
        const float* __restrict__ rn0g, const float* __restrict__ rn1g,
        const float* __restrict__ cvg, const float* __restrict__ svg,
        const float* __restrict__ mug,
        const float* __restrict__ w3g, const float* __restrict__ b3g,
        const unsigned short* __restrict__ wimg,
        float* __restrict__ out, unsigned char* sm, uint32_t sb)
{
  const int tid = threadIdx.x, lane = tid & 31, wid = tid >> 5;
  const int wm = wid & 3, wn = wid >> 2;
  const int m15 = wm*32 + (lane & 15);
  const int row0 = bid * TILE_M;

  float* w3s = (float*)(sm + OFF_W3);
  float* b3s = (float*)(sm + OFF_B3);
  float* mus = (float*)(sm + OFF_MU);
  int*   idxs = (int*)(sm + OFF_IDX);
  float* rns = (float*)(sm + OFF_RN);
  float* css = (float*)(sm + OFF_CS);
  float* sss = (float*)(sm + OFF_SS);

  if (tid < 128){
    idxs[tid]       = i0[row0 + tid];
    idxs[128 + tid] = i1[row0 + tid];
    rns[tid]        = rn0g[row0 + tid];
    if (TRIP){
      idxs[256 + tid] = i2[row0 + tid];
      rns[128 + tid]  = rn1g[row0 + tid];
      css[tid]        = cvg[row0 + tid];
      sss[tid]        = svg[row0 + tid];
    }
  }
  if (tid < 100) mus[tid] = mug[tid];
  for (int i = tid; i < 768; i += NTH) w3s[i] = w3g[i];
  if (tid < 3) b3s[tid] = b3g[tid];
  __syncthreads();

  float acc[2][8][4];

  auto feat = [&](int k, int r) -> float {
    if (!TRIP){
      int b = k - 256;
      if ((unsigned)b < 100u){ float d = mus[b] - rns[r]; return __expf(-10.0f * d * d); }
      return 0.0f;
    } else {
      if (k < 484){
        int b = k - 384;
        if (b >= 0 && b < 100){ float d = mus[b] - rns[r]; return __expf(-10.0f * d * d); }
        return 0.0f;
      } else if (k < 584){
        float d = mus[k - 484] - rns[128 + r];
        return __expf(-10.0f * d * d);
      } else if (k == 584) return css[r];
      else if (k == 585)   return sss[r];
      return 0.0f;
    }
  };

  // build layer-0 chunk c (128 rows x 64 k-cols fp16), 128B rows, 8-unit swizzle
  auto genchunk = [&](int c, int slot){
    const int r  = tid & 127;
    const int gb = (tid >> 7) * 2;
    const int k0 = c * 64;
    unsigned char* hb = sm + X0_OFF + slot * 16384;
    #pragma unroll
    for (int g = 0; g < 2; g++){
      const int u = gb + g;
      const int kk = k0 + u * 8;
      float4 f0, f1;
      if (k0 < KGATH){
        const float* src = h + (size_t)idxs[(kk >> 7) * 128 + r] * 128 + (kk & 127);
        f0 = *(const float4*)src;
        f1 = *(const float4*)(src + 4);
      } else {
        f0.x = feat(kk,   r); f0.y = feat(kk+1, r); f0.z = feat(kk+2, r); f0.w = feat(kk+3, r);
        f1.x = feat(kk+4, r); f1.y = feat(kk+5, r); f1.z = feat(kk+6, r); f1.w = feat(kk+7, r);
      }
      uint4 v;
      v.x = pack_h2(f0.x, f0.y);
      v.y = pack_h2(f0.z, f0.w);
      v.z = pack_h2(f1.x, f1.y);
      v.w = pack_h2(f1.z, f1.w);
      const uint32_t off = (uint32_t)(r * 128 + ((((unsigned)u) ^ (unsigned)(r & 7)) << 4));
      *(uint4*)(hb + off) = v;
    }
  };

  // stage one 16KB W unit into ring slot
  auto stageUnit = [&](const unsigned short* wbase, int u, int slot){
    const char* s = (const char*)wbase + (size_t)u * 16384 + tid * 16;
    uint32_t d = sb + W_BUF + (uint32_t)(slot * 16384) + tid * 16;
    cp16s(d, s);
    cp16s(d + 8192, s + 8192);
    cp_commit();
  };

  // stream nu 32-k chunks; 4-deep ring, one barrier/chunk; prefetch next layer's
  // first 3 units during the tail so cp_wait<2> holds at every iteration.
  auto run_layer = [&](int nu, const unsigned short* wbase, bool isL0,
                       const unsigned short* nextbase, bool prestaged){
    #pragma unroll
    for (int t = 0; t < 2; t++)
      #pragma unroll
      for (int j = 0; j < 8; j++)
        #pragma unroll
        for (int q = 0; q < 4; q++) acc[t][j][q] = 0.0f;
    if (!prestaged){
      stageUnit(wbase, 0, 0);
      stageUnit(wbase, 1, 1);
      stageUnit(wbase, 2, 2);
    }
    for (int p = 0; p < nu; p++){
      if (nextbase)            cp_wait<2>();
      else if (p <= nu - 3)    cp_wait<2>();
      else if (p == nu - 2)    cp_wait<1>();
      else                     cp_wait<0>();
      __syncthreads();
      const int ps = p + 3;
      if (ps < nu)                               stageUnit(wbase, ps, ps & 3);
      else if (nextbase && ps - nu < 3)          stageUnit(nextbase, ps - nu, ps & 3);
      if (isL0 && !(p & 1) && ((p >> 1) + 1 < (nu >> 1)))
        genchunk((p >> 1) + 1, ((p >> 1) + 1) & 1);
      const uint32_t wB = sb + W_BUF + (uint32_t)((p & 3) * 16384);
      if (isL0){
        const uint32_t xb = sb + X0_OFF + (uint32_t)(((p >> 1) & 1) * 16384);
        pass_single(acc, xb, 128, (p & 1) * 4, wB, lane, wn, m15);
      } else {
        pass_single(acc, sb + ACT16, 512, p * 4, wB, lane, wn, m15);
      }
    }
  };

  // epilogue: silu(acc) -> fp16 ACT (512B rows, swizzled)
  auto epi_act = [&](){
    #pragma unroll
    for (int t = 0; t < 2; t++){
      #pragma unroll
      for (int j = 0; j < 8; j++){
        const int r  = wm*32 + t*16 + (lane >> 2);
        const int cc = wn*64 + j*8 + (lane & 3) * 2;
        float s0 = silu_f(acc[t][j][0]);
        float s1 = silu_f(acc[t][j][1]);
        float s2 = silu_f(acc[t][j][2]);
        float s3 = silu_f(acc[t][j][3]);
        const uint32_t coff = (uint32_t)(((((unsigned)(cc >> 3)) ^ (unsigned)(r & 7)) << 4) + (cc & 7) * 2);
        *(uint32_t*)(sm + ACT16 + r * 512 + coff) = pack_h2(s0, s1);
        const int r2 = r + 8;
        const uint32_t coff2 = (uint32_t)(((((unsigned)(cc >> 3)) ^ (unsigned)(r2 & 7)) << 4) + (cc & 7) * 2);
        *(uint32_t*)(sm + ACT16 + r2 * 512 + coff2) = pack_h2(s2, s3);
      }
    }
  };

  const unsigned short* w1 = wimg + (size_t)NU0 * 8192;
  const unsigned short* w2 = wimg + (size_t)(NU0 + 8) * 8192;

  // ---- layer 0 ----
  genchunk(0, 0);
  run_layer(NU0, wimg, true, w1, false);
  __syncthreads();            // X0 reads done before ACT overwrite
  epi_act();
  __syncthreads();
  // ---- layer 1 ----
  run_layer(8, w1, false, w2, true);
  __syncthreads();
  epi_act();
  __syncthreads();
  // ---- layer 2 ----
  run_layer(8, w2, false, (const unsigned short*)0, true);
  __syncthreads();            // ACT reads done before F32 overwrite
  {
    float* actf = (float*)(sm + F32BUF);
    #pragma unroll
    for (int t = 0; t < 2; t++){
      #pragma unroll
      for (int j = 0; j < 8; j++){
        const int r  = wm*32 + t*16 + (lane >> 2);
        const int cc = wn*64 + j*8 + (lane & 3) * 2;
        actf[r * 257 + cc]           = silu_f(acc[t][j][0]);
        actf[r * 257 + cc + 1]       = silu_f(acc[t][j][1]);
        actf[(r + 8) * 257 + cc]     = silu_f(acc[t][j][2]);
        actf[(r + 8) * 257 + cc + 1] = silu_f(acc[t][j][3]);
      }
    }
  }
  __syncthreads();
  // ---- layer 3: [128 x 256] @ W3[256 x 3] + b3, all 512 threads ----
  {
    float* part = (float*)(sm + PARTS);     // W ring dead
    const float* actf = (const float*)(sm + F32BUF);
    const int r = tid >> 2, q = tid & 3;
    float a0 = 0.f, a1 = 0.f, a2 = 0.f;
    const int k0 = q * 64;
    #pragma unroll 16
    for (int k = k0; k < k0 + 64; k++){
      float v = actf[r * 257 + k];
      a0 = fmaf(v, w3s[k * 3 + 0], a0);
      a1 = fmaf(v, w3s[k * 3 + 1], a1);
      a2 = fmaf(v, w3s[k * 3 + 2], a2);
    }
    part[(r * 4 + q) * 3 + 0] = a0;
    part[(r * 4 + q) * 3 + 1] = a1;
    part[(r * 4 + q) * 3 + 2] = a2;
    __syncthreads();
    if (tid < 384){
      const int rr = tid / 3, o = tid - rr * 3;
      float s = b3s[o]
              + part[(rr * 4 + 0) * 3 + o] + part[(rr * 4 + 1) * 3 + o]
              + part[(rr * 4 + 2) * 3 + o] + part[(rr * 4 + 3) * 3 + o];
      out[(size_t)(row0 + rr) * 3 + o] = s;
    }
  }
}

__global__ void __launch_bounds__(NTH, 1)
mlp_all(const float* __restrict__ h,
        const int* __restrict__ src, const int* __restrict__ dst,
        const float* __restrict__ enorm,
        const int* __restrict__ tsrc, const int* __restrict__ tdi, const int* __restrict__ tdj,
        const float* __restrict__ nij, const float* __restrict__ nik,
        const float* __restrict__ cosv, const float* __restrict__ sinv,
        const float* __restrict__ mu,
        const float* __restrict__ eW3, const float* __restrict__ eb3,
        const float* __restrict__ tW3, const float* __restrict__ tb3,
        float* __restrict__ out)
{
  extern __shared__ __align__(1024) unsigned char sm[];
  const uint32_t sb = smem_u32(sm);
  const int bid = blockIdx.x;
  if (bid < NBLK_E){
    mlp_body<false, 256, 12>(bid, h, src, dst, dst, enorm, enorm, enorm, enorm, mu,
                             eW3, eb3, (const unsigned short*)g_wimg_e, out, sm, sb);
  } else {
    mlp_body<true, 384, 20>(bid - NBLK_E, h, tsrc, tdi, tdj, nij, nik, cosv, sinv, mu,
                            tW3, tb3, (const unsigned short*)g_wimg_t,
                            out + (size_t)NEDGE * 3, sm, sb);
  }
}

extern "C" void kernel_launch(void* const* d_in, const int* in_sizes, int n_in,
                              void* d_out, int out_size){
  const float* h     = (const float*)d_in[0];
  const int*   src   = (const int*)  d_in[1];
  const int*   dst   = (const int*)  d_in[2];
  const float* enorm = (const float*)d_in[3];
  const int*   tsrc  = (const int*)  d_in[4];
  const int*   tdi   = (const int*)  d_in[5];
  const int*   tdj   = (const int*)  d_in[6];
  const float* nij   = (const float*)d_in[7];
  const float* nik   = (const float*)d_in[8];
  const float* cosv  = (const float*)d_in[9];
  const float* sinv  = (const float*)d_in[10];
  const float* mu    = (const float*)d_in[11];
  const float* eW0   = (const float*)d_in[12];
  const float* eW1   = (const float*)d_in[13];
  const float* eW2   = (const float*)d_in[14];
  const float* eW3   = (const float*)d_in[15];
  const float* eb3   = (const float*)d_in[16];
  const float* tW0   = (const float*)d_in[17];
  const float* tW1   = (const float*)d_in[18];
  const float* tW2   = (const float*)d_in[19];
  const float* tW3   = (const float*)d_in[20];
  const float* tb3   = (const float*)d_in[21];
  float* out = (float*)d_out;

  prep_all<<<dim3(640, 6), 256>>>(eW0, eW1, eW2, tW0, tW1, tW2);

  cudaFuncSetAttribute(mlp_all, cudaFuncAttributeMaxDynamicSharedMemorySize, SMEM_TOTAL);
  mlp_all<<<NBLK_E + NBLK_T, NTH, SMEM_TOTAL>>>(
      h, src, dst, enorm, tsrc, tdi, tdj, nij, nik, cosv, sinv, mu,
      eW3, eb3, tW3, tb3, out);
}

// round 8
// speedup vs baseline: 4.9492x; 1.0710x over previous
#include <cuda_runtime.h>
#include <cuda_fp16.h>
#include <stdint.h>

#define NEDGE 262144
#define NTRI  393216
#define TILE_M 128
#define NTH   512
#define NBLK_E (NEDGE/TILE_M)   // 2048
#define NBLK_T (NTRI/TILE_M)    // 3072

// ---- smem byte offsets ----
#define W_BUF   0            // 4 slots x 32768 = 131072
#define ACT16   131072       // 65536 (128 rows x 512B fp16)
#define X0_OFF  131072       // 2 slots x 16384 (layer0 ring; overlaps ACT, dead after L0)
#define F32BUF  0            // layer-3 fp32 act 131584B (overlaps W ring + ACT head, after L2)
#define PARTS   190464       // L3 partials 6144B (inside dead ACT16, ends at MISC)
#define MISC    196608
#define OFF_W3  (MISC)
#define OFF_B3  (MISC+3072)
#define OFF_MU  (MISC+3088)
#define OFF_IDX (MISC+3504)
#define OFF_RN  (MISC+5040)
#define OFF_CS  (MISC+6064)
#define OFF_SS  (MISC+6576)
#define SMEM_TOTAL (MISC+7168)   // 203776

// weight images: units of 32k x 256n fp16 (8192 u16 = 16KB); pairs of units = 64-k.
// edges: L0 12 units @0, L1 8 @12, L2 8 @20.  trip: L0 20 @0, L1 8 @20, L2 8 @28.
__device__ __align__(16) unsigned short g_wimg_e[229376]; // 28 units
__device__ __align__(16) unsigned short g_wimg_t[294912]; // 36 units

__device__ __forceinline__ uint32_t smem_u32(const void* p){
  uint32_t a;
  asm("{ .reg .u64 t; cvta.to.shared.u64 t, %1; cvt.u32.u64 %0, t; }" : "=r"(a) : "l"(p));
  return a;
}
__device__ __forceinline__ void cp16s(uint32_t dst, const void* src){
  asm volatile("cp.async.cg.shared.global [%0], [%1], 16;" :: "r"(dst), "l"(src) : "memory");
}
__device__ __forceinline__ void cp_commit(){ asm volatile("cp.async.commit_group;" ::: "memory"); }
template<int N> __device__ __forceinline__ void cp_wait(){ asm volatile("cp.async.wait_group %0;" :: "n"(N) : "memory"); }

__device__ __forceinline__ void ldsm4(uint32_t (&r)[4], uint32_t a){
  asm volatile("ldmatrix.sync.aligned.m8n8.x4.shared.b16 {%0,%1,%2,%3}, [%4];"
    : "=r"(r[0]), "=r"(r[1]), "=r"(r[2]), "=r"(r[3]) : "r"(a));
}
__device__ __forceinline__ void ldsm4t(uint32_t (&r)[4], uint32_t a){
  asm volatile("ldmatrix.sync.aligned.m8n8.x4.trans.shared.b16 {%0,%1,%2,%3}, [%4];"
    : "=r"(r[0]), "=r"(r[1]), "=r"(r[2]), "=r"(r[3]) : "r"(a));
}
__device__ __forceinline__ void mma_fp(float (&d)[4], const uint32_t (&a)[4], uint32_t b0, uint32_t b1){
  asm volatile("mma.sync.aligned.m16n8k16.row.col.f32.f16.f16.f32 "
    "{%0,%1,%2,%3}, {%4,%5,%6,%7}, {%8,%9}, {%0,%1,%2,%3};"
    : "+f"(d[0]), "+f"(d[1]), "+f"(d[2]), "+f"(d[3])
    : "r"(a[0]), "r"(a[1]), "r"(a[2]), "r"(a[3]), "r"(b0), "r"(b1));
}

__device__ __forceinline__ uint32_t pack_h2(float x, float y){
  __half2 t = __floats2half2_rn(x, y);
  return *(uint32_t*)&t;
}
__device__ __forceinline__ float silu_f(float x){
  return __fdividef(x, 1.0f + __expf(-x));
}

// One 32-k sub-chunk, single pass: D += A*W (fp16). 12 LDSM, 32 HMMA, warp tile 32x64.
__device__ __forceinline__ void pass_single(float (&acc)[2][8][4],
    uint32_t aB, int aRB, int kub, uint32_t wB, int lane, int wn, int m15){
  #pragma unroll
  for (int ks = 0; ks < 2; ks++){
    const int ku = kub + ks*2 + (lane >> 4);
    const uint32_t sw = (uint32_t)((ku ^ (lane & 7)) << 4);
    const uint32_t ro = (uint32_t)(m15 * aRB);
    uint32_t a0[4], a1[4];
    ldsm4(a0, aB + ro + sw);
    ldsm4(a1, aB + ro + 16*aRB + sw);
    const uint32_t wro = (uint32_t)((ks*16 + (lane & 15)) * 512);
    #pragma unroll
    for (int jj = 0; jj < 4; jj++){
      const int nu = wn*8 + jj*2 + (lane >> 4);
      const uint32_t nsw = (uint32_t)((nu ^ (lane & 7)) << 4);
      uint32_t b[4];
      ldsm4t(b, wB + wro + nsw);
      mma_fp(acc[0][2*jj],   a0, b[0], b[1]);
      mma_fp(acc[0][2*jj+1], a0, b[2], b[3]);
      mma_fp(acc[1][2*jj],   a1, b[0], b[1]);
      mma_fp(acc[1][2*jj+1], a1, b[2], b[3]);
    }
  }
}

// ---- weight prep: all 6 matrices, fp16, pre-swizzled 16KB units ----
__global__ void prep_all(const float* __restrict__ eW0, const float* __restrict__ eW1,
                         const float* __restrict__ eW2, const float* __restrict__ tW0,
                         const float* __restrict__ tW1, const float* __restrict__ tW2){
  const int job = blockIdx.y;
  const float* W; unsigned short* img; int KIN, Kpad;
  switch (job){
    case 0: W = eW0; img = g_wimg_e;                     KIN = 356; Kpad = 384; break;
    case 1: W = eW1; img = g_wimg_e + (size_t)12*8192;   KIN = 256; Kpad = 256; break;
    case 2: W = eW2; img = g_wimg_e + (size_t)20*8192;   KIN = 256; Kpad = 256; break;
    case 3: W = tW0; img = g_wimg_t;                     KIN = 586; Kpad = 640; break;
    case 4: W = tW1; img = g_wimg_t + (size_t)20*8192;   KIN = 256; Kpad = 256; break;
    default:W = tW2; img = g_wimg_t + (size_t)28*8192;   KIN = 256; Kpad = 256; break;
  }
  int gid = blockIdx.x * blockDim.x + threadIdx.x;
  if (gid >= Kpad * 256) return;
  int k = gid >> 8, n = gid & 255;
  float x = (k < KIN) ? W[k * 256 + n] : 0.0f;
  __half hb = __float2half_rn(x);
  int c = k >> 5, kin = k & 31;
  int idx16 = kin * 256 + (((n >> 3) ^ (kin & 7)) << 3) + (n & 7);
  img[(size_t)c * 8192 + idx16] = *(unsigned short*)&hb;
}

// ---------------- fused MLP body ----------------
// NP0 = # of 64-k pairs for layer0 (edges 6, trip 10)
template<bool TRIP, int KGATH, int NP0>
__device__ __forceinline__ void mlp_body(int bid,
        const float* __restrict__ h,
        const int* __restrict__ i0, const int* __restrict__ i1, const int* __restrict__ i2,
        const float* __restrict__ rn0g, const float* __restrict__ rn1g,
        const float* __restrict__ cvg, const float* __restrict__ svg,
        const float* __restrict__ mug,
        const float* __restrict__ w3g, const float* __restrict__ b3g,
        const unsigned short* __restrict__ wimg,
        float* __restrict__ out, unsigned char* sm, uint32_t sb)
{
  const int tid = threadIdx.x, lane = tid & 31, wid = tid >> 5;
  const int wm = wid & 3, wn = wid >> 2;
  const int m15 = wm*32 + (lane & 15);
  const int row0 = bid * TILE_M;

  float* w3s = (float*)(sm + OFF_W3);
  float* b3s = (float*)(sm + OFF_B3);
  float* mus = (float*)(sm + OFF_MU);
  int*   idxs = (int*)(sm + OFF_IDX);
  float* rns = (float*)(sm + OFF_RN);
  float* css = (float*)(sm + OFF_CS);
  float* sss = (float*)(sm + OFF_SS);

  if (tid < 128){
    idxs[tid]       = i0[row0 + tid];
    idxs[128 + tid] = i1[row0 + tid];
    rns[tid]        = rn0g[row0 + tid];
    if (TRIP){
      idxs[256 + tid] = i2[row0 + tid];
      rns[128 + tid]  = rn1g[row0 + tid];
      css[tid]        = cvg[row0 + tid];
      sss[tid]        = svg[row0 + tid];
    }
  }
  if (tid < 100) mus[tid] = mug[tid];
  for (int i = tid; i < 768; i += NTH) w3s[i] = w3g[i];
  if (tid < 3) b3s[tid] = b3g[tid];
  __syncthreads();

  float acc[2][8][4];

  auto feat = [&](int k, int r) -> float {
    if (!TRIP){
      int b = k - 256;
      if ((unsigned)b < 100u){ float d = mus[b] - rns[r]; return __expf(-10.0f * d * d); }
      return 0.0f;
    } else {
      if (k < 484){
        int b = k - 384;
        if (b >= 0 && b < 100){ float d = mus[b] - rns[r]; return __expf(-10.0f * d * d); }
        return 0.0f;
      } else if (k < 584){
        float d = mus[k - 484] - rns[128 + r];
        return __expf(-10.0f * d * d);
      } else if (k == 584) return css[r];
      else if (k == 585)   return sss[r];
      return 0.0f;
    }
  };

  // build layer-0 chunk c (128 rows x 64 k-cols fp16). 4 threads per row:
  // warp covers 8 rows x 256B contiguous gather (good coalescing).
  auto genchunk = [&](int c, int slot){
    const int r = tid >> 2, q = tid & 3;
    const int k0 = c * 64 + q * 16;
    unsigned char* hb = sm + X0_OFF + slot * 16384;
    float4 f[4];
    if (c * 64 < KGATH){
      const float4* src = (const float4*)(h + (size_t)idxs[(c >> 1) * 128 + r] * 128 + (k0 & 127));
      f[0] = src[0]; f[1] = src[1]; f[2] = src[2]; f[3] = src[3];
    } else {
      #pragma unroll
      for (int g = 0; g < 4; g++){
        int kk = k0 + g * 4;
        f[g].x = feat(kk, r);   f[g].y = feat(kk+1, r);
        f[g].z = feat(kk+2, r); f[g].w = feat(kk+3, r);
      }
    }
    #pragma unroll
    for (int hf = 0; hf < 2; hf++){
      uint4 v;
      v.x = pack_h2(f[2*hf].x,   f[2*hf].y);
      v.y = pack_h2(f[2*hf].z,   f[2*hf].w);
      v.z = pack_h2(f[2*hf+1].x, f[2*hf+1].y);
      v.w = pack_h2(f[2*hf+1].z, f[2*hf+1].w);
      const unsigned u = (unsigned)(q * 2 + hf);
      const uint32_t off = (uint32_t)(r * 128 + ((u ^ (unsigned)(r & 7)) << 4));
      *(uint4*)(hb + off) = v;
    }
  };

  // stage one 32KB pair (two 16KB units) into a ring slot; one commit group
  auto stagePair = [&](const unsigned short* wbase, int pr, int slot){
    const char* s = (const char*)wbase + (size_t)pr * 32768 + tid * 16;
    uint32_t d = sb + W_BUF + (uint32_t)(slot * 32768) + tid * 16;
    #pragma unroll
    for (int i = 0; i < 4; i++) cp16s(d + i * 8192, s + i * 8192);
    cp_commit();
  };

  // stream npair 64-k pairs; one barrier per pair; 4-deep ring with explicit
  // slot counter s0; prefetch next layer's first 3 pairs during the tail.
  auto run_layer = [&](int npair, const unsigned short* wbase, bool isL0,
                       const unsigned short* nextbase, bool prestaged, int s0){
    #pragma unroll
    for (int t = 0; t < 2; t++)
      #pragma unroll
      for (int j = 0; j < 8; j++)
        #pragma unroll
        for (int q = 0; q < 4; q++) acc[t][j][q] = 0.0f;
    if (!prestaged){
      stagePair(wbase, 0, s0 & 3);
      stagePair(wbase, 1, (s0 + 1) & 3);
      stagePair(wbase, 2, (s0 + 2) & 3);
    }
    for (int p = 0; p < npair; p++){
      if (nextbase || p <= npair - 3) cp_wait<2>();
      else if (p == npair - 2)        cp_wait<1>();
      else                            cp_wait<0>();
      __syncthreads();
      const int ps = p + 3;
      if (ps < npair)                       stagePair(wbase, ps, (s0 + ps) & 3);
      else if (nextbase && ps - npair < 3)  stagePair(nextbase, ps - npair, (s0 + ps) & 3);
      const uint32_t wB = sb + W_BUF + (uint32_t)(((s0 + p) & 3) * 32768);
      if (isL0){
        const uint32_t xb = sb + X0_OFF + (uint32_t)((p & 1) * 16384);
        pass_single(acc, xb, 128, 0, wB, lane, wn, m15);
        if (p + 1 < npair) genchunk(p + 1, (p + 1) & 1);
        pass_single(acc, xb, 128, 4, wB + 16384, lane, wn, m15);
      } else {
        pass_single(acc, sb + ACT16, 512, p * 8,     wB,         lane, wn, m15);
        pass_single(acc, sb + ACT16, 512, p * 8 + 4, wB + 16384, lane, wn, m15);
      }
    }
  };

  // epilogue: silu(acc) -> fp16 ACT (512B rows, swizzled)
  auto epi_act = [&](){
    #pragma unroll
    for (int t = 0; t < 2; t++){
      #pragma unroll
      for (int j = 0; j < 8; j++){
        const int r  = wm*32 + t*16 + (lane >> 2);
        const int cc = wn*64 + j*8 + (lane & 3) * 2;
        float s0 = silu_f(acc[t][j][0]);
        float s1 = silu_f(acc[t][j][1]);
        float s2 = silu_f(acc[t][j][2]);
        float s3 = silu_f(acc[t][j][3]);
        const uint32_t coff = (uint32_t)(((((unsigned)(cc >> 3)) ^ (unsigned)(r & 7)) << 4) + (cc & 7) * 2);
        *(uint32_t*)(sm + ACT16 + r * 512 + coff) = pack_h2(s0, s1);
        const int r2 = r + 8;
        const uint32_t coff2 = (uint32_t)(((((unsigned)(cc >> 3)) ^ (unsigned)(r2 & 7)) << 4) + (cc & 7) * 2);
        *(uint32_t*)(sm + ACT16 + r2 * 512 + coff2) = pack_h2(s2, s3);
      }
    }
  };

  const unsigned short* w1 = wimg + (size_t)(2 * NP0) * 8192;
  const unsigned short* w2 = wimg + (size_t)(2 * NP0 + 8) * 8192;
  int s0 = 0;

  // ---- layer 0 ----
  genchunk(0, 0);
  run_layer(NP0, wimg, true, w1, false, s0);
  s0 = (s0 + NP0) & 3;
  __syncthreads();            // X0 reads done before ACT overwrite
  epi_act();
  __syncthreads();
  // ---- layer 1 ----
  run_layer(4, w1, false, w2, true, s0);
  s0 = (s0 + 4) & 3;
  __syncthreads();
  epi_act();
  __syncthreads();
  // ---- layer 2 ----
  run_layer(4, w2, false, (const unsigned short*)0, true, s0);
  __syncthreads();            // ACT/W reads done before F32 overwrite
  {
    float* actf = (float*)(sm + F32BUF);
    #pragma unroll
    for (int t = 0; t < 2; t++){
      #pragma unroll
      for (int j = 0; j < 8; j++){
        const int r  = wm*32 + t*16 + (lane >> 2);
        const int cc = wn*64 + j*8 + (lane & 3) * 2;
        actf[r * 257 + cc]           = silu_f(acc[t][j][0]);
        actf[r * 257 + cc + 1]       = silu_f(acc[t][j][1]);
        actf[(r + 8) * 257 + cc]     = silu_f(acc[t][j][2]);
        actf[(r + 8) * 257 + cc + 1] = silu_f(acc[t][j][3]);
      }
    }
  }
  __syncthreads();
  // ---- layer 3: [128 x 256] @ W3[256 x 3] + b3, all 512 threads ----
  {
    float* part = (float*)(sm + PARTS);
    const float* actf = (const float*)(sm + F32BUF);
    const int r = tid >> 2, q = tid & 3;
    float a0 = 0.f, a1 = 0.f, a2 = 0.f;
    const int k0 = q * 64;
    #pragma unroll 16
    for (int k = k0; k < k0 + 64; k++){
      float v = actf[r * 257 + k];
      a0 = fmaf(v, w3s[k * 3 + 0], a0);
      a1 = fmaf(v, w3s[k * 3 + 1], a1);
      a2 = fmaf(v, w3s[k * 3 + 2], a2);
    }
    part[(r * 4 + q) * 3 + 0] = a0;
    part[(r * 4 + q) * 3 + 1] = a1;
    part[(r * 4 + q) * 3 + 2] = a2;
    __syncthreads();
    if (tid < 384){
      const int rr = tid / 3, o = tid - rr * 3;
      float s = b3s[o]
              + part[(rr * 4 + 0) * 3 + o] + part[(rr * 4 + 1) * 3 + o]
              + part[(rr * 4 + 2) * 3 + o] + part[(rr * 4 + 3) * 3 + o];
      out[(size_t)(row0 + rr) * 3 + o] = s;
    }
  }
}

__global__ void __launch_bounds__(NTH, 1)
mlp_all(const float* __restrict__ h,
        const int* __restrict__ src, const int* __restrict__ dst,
        const float* __restrict__ enorm,
        const int* __restrict__ tsrc, const int* __restrict__ tdi, const int* __restrict__ tdj,
        const float* __restrict__ nij, const float* __restrict__ nik,
        const float* __restrict__ cosv, const float* __restrict__ sinv,
        const float* __restrict__ mu,
        const float* __restrict__ eW3, const float* __restrict__ eb3,
        const float* __restrict__ tW3, const float* __restrict__ tb3,
        float* __restrict__ out)
{
  extern __shared__ __align__(1024) unsigned char sm[];
  const uint32_t sb = smem_u32(sm);
  const int bid = blockIdx.x;
  if (bid < NBLK_E){
    mlp_body<false, 256, 6>(bid, h, src, dst, dst, enorm, enorm, enorm, enorm, mu,
                            eW3, eb3, (const unsigned short*)g_wimg_e, out, sm, sb);
  } else {
    mlp_body<true, 384, 10>(bid - NBLK_E, h, tsrc, tdi, tdj, nij, nik, cosv, sinv, mu,
                            tW3, tb3, (const unsigned short*)g_wimg_t,
                            out + (size_t)NEDGE * 3, sm, sb);
  }
}

extern "C" void kernel_launch(void* const* d_in, const int* in_sizes, int n_in,
                              void* d_out, int out_size){
  const float* h     = (const float*)d_in[0];
  const int*   src   = (const int*)  d_in[1];
  const int*   dst   = (const int*)  d_in[2];
  const float* enorm = (const float*)d_in[3];
  const int*   tsrc  = (const int*)  d_in[4];
  const int*   tdi   = (const int*)  d_in[5];
  const int*   tdj   = (const int*)  d_in[6];
  const float* nij   = (const float*)d_in[7];
  const float* nik   = (const float*)d_in[8];
  const float* cosv  = (const float*)d_in[9];
  const float* sinv  = (const float*)d_in[10];
  const float* mu    = (const float*)d_in[11];
  const float* eW0   = (const float*)d_in[12];
  const float* eW1   = (const float*)d_in[13];
  const float* eW2   = (const float*)d_in[14];
  const float* eW3   = (const float*)d_in[15];
  const float* eb3   = (const float*)d_in[16];
  const float* tW0   = (const float*)d_in[17];
  const float* tW1   = (const float*)d_in[18];
  const float* tW2   = (const float*)d_in[19];
  const float* tW3   = (const float*)d_in[20];
  const float* tb3   = (const float*)d_in[21];
  float* out = (float*)d_out;

  prep_all<<<dim3(640, 6), 256>>>(eW0, eW1, eW2, tW0, tW1, tW2);

  cudaFuncSetAttribute(mlp_all, cudaFuncAttributeMaxDynamicSharedMemorySize, SMEM_TOTAL);
  mlp_all<<<NBLK_E + NBLK_T, NTH, SMEM_TOTAL>>>(
      h, src, dst, enorm, tsrc, tdi, tdj, nij, nik, cosv, sinv, mu,
      eW3, eb3, tW3, tb3, out);
}

// round 9
// speedup vs baseline: 5.0235x; 1.0150x over previous
#include <cuda_runtime.h>
#include <cuda_fp16.h>
#include <stdint.h>

#define NEDGE 262144
#define NTRI  393216
#define TILE_M 64
#define NTH   256
#define NBLK_E (NEDGE/TILE_M)   // 4096
#define NBLK_T (NTRI/TILE_M)    // 6144

// ---- smem byte offsets (per CTA) ----
#define W_BUF   0            // 4 slots x 16384 = 65536
#define ACT16   65536        // 32768 (64 rows x 512B fp16)
#define X0_OFF  65536        // 2 slots x 8192 (layer0 ring; overlaps ACT, dead after L0)
#define F32BUF  0            // layer-3 fp32 act 64x257x4=65792B (overlaps W ring + ACT head)
#define PARTS   66048        // L3 partials 3072B (inside dead ACT16)
#define MISC    98304
#define OFF_W3  (MISC)
#define OFF_B3  (MISC+3072)
#define OFF_MU  (MISC+3088)
#define OFF_IDX (MISC+3504)  // 3*64 ints
#define OFF_RN  (MISC+4272)  // 2*64 floats
#define OFF_CS  (MISC+4784)
#define OFF_SS  (MISC+5040)
#define SMEM_TOTAL (MISC+5376)   // 103680 -> 2 CTAs/SM

// weight images: units of 32k x 256n fp16 (8192 u16 = 16KB).
// edges: L0 12 units @0, L1 8 @12, L2 8 @20.  trip: L0 20 @0, L1 8 @20, L2 8 @28.
__device__ __align__(16) unsigned short g_wimg_e[229376]; // 28 units
__device__ __align__(16) unsigned short g_wimg_t[294912]; // 36 units

__device__ __forceinline__ uint32_t smem_u32(const void* p){
  uint32_t a;
  asm("{ .reg .u64 t; cvta.to.shared.u64 t, %1; cvt.u32.u64 %0, t; }" : "=r"(a) : "l"(p));
  return a;
}
__device__ __forceinline__ void cp16s(uint32_t dst, const void* src){
  asm volatile("cp.async.cg.shared.global [%0], [%1], 16;" :: "r"(dst), "l"(src) : "memory");
}
__device__ __forceinline__ void cp_commit(){ asm volatile("cp.async.commit_group;" ::: "memory"); }
template<int N> __device__ __forceinline__ void cp_wait(){ asm volatile("cp.async.wait_group %0;" :: "n"(N) : "memory"); }

__device__ __forceinline__ void ldsm4(uint32_t (&r)[4], uint32_t a){
  asm volatile("ldmatrix.sync.aligned.m8n8.x4.shared.b16 {%0,%1,%2,%3}, [%4];"
    : "=r"(r[0]), "=r"(r[1]), "=r"(r[2]), "=r"(r[3]) : "r"(a));
}
__device__ __forceinline__ void ldsm4t(uint32_t (&r)[4], uint32_t a){
  asm volatile("ldmatrix.sync.aligned.m8n8.x4.trans.shared.b16 {%0,%1,%2,%3}, [%4];"
    : "=r"(r[0]), "=r"(r[1]), "=r"(r[2]), "=r"(r[3]) : "r"(a));
}
__device__ __forceinline__ void mma_fp(float (&d)[4], const uint32_t (&a)[4], uint32_t b0, uint32_t b1){
  asm volatile("mma.sync.aligned.m16n8k16.row.col.f32.f16.f16.f32 "
    "{%0,%1,%2,%3}, {%4,%5,%6,%7}, {%8,%9}, {%0,%1,%2,%3};"
    : "+f"(d[0]), "+f"(d[1]), "+f"(d[2]), "+f"(d[3])
    : "r"(a[0]), "r"(a[1]), "r"(a[2]), "r"(a[3]), "r"(b0), "r"(b1));
}

__device__ __forceinline__ uint32_t pack_h2(float x, float y){
  __half2 t = __floats2half2_rn(x, y);
  return *(uint32_t*)&t;
}
__device__ __forceinline__ float silu_f(float x){
  return __fdividef(x, 1.0f + __expf(-x));
}

// One 32-k unit, single pass: D += A*W (fp16). 12 LDSM, 32 HMMA, warp tile 32x64.
__device__ __forceinline__ void pass_single(float (&acc)[2][8][4],
    uint32_t aB, int aRB, int kub, uint32_t wB, int lane, int wn, int m15){
  #pragma unroll
  for (int ks = 0; ks < 2; ks++){
    const int ku = kub + ks*2 + (lane >> 4);
    const uint32_t sw = (uint32_t)((ku ^ (lane & 7)) << 4);
    const uint32_t ro = (uint32_t)(m15 * aRB);
    uint32_t a0[4], a1[4];
    ldsm4(a0, aB + ro + sw);
    ldsm4(a1, aB + ro + 16*aRB + sw);
    const uint32_t wro = (uint32_t)((ks*16 + (lane & 15)) * 512);
    #pragma unroll
    for (int jj = 0; jj < 4; jj++){
      const int nu = wn*8 + jj*2 + (lane >> 4);
      const uint32_t nsw = (uint32_t)((nu ^ (lane & 7)) << 4);
      uint32_t b[4];
      ldsm4t(b, wB + wro + nsw);
      mma_fp(acc[0][2*jj],   a0, b[0], b[1]);
      mma_fp(acc[0][2*jj+1], a0, b[2], b[3]);
      mma_fp(acc[1][2*jj],   a1, b[0], b[1]);
      mma_fp(acc[1][2*jj+1], a1, b[2], b[3]);
    }
  }
}

// ---- weight prep: all 6 matrices, fp16, pre-swizzled 16KB units ----
__global__ void prep_all(const float* __restrict__ eW0, const float* __restrict__ eW1,
                         const float* __restrict__ eW2, const float* __restrict__ tW0,
                         const float* __restrict__ tW1, const float* __restrict__ tW2){
  const int job = blockIdx.y;
  const float* W; unsigned short* img; int KIN, Kpad;
  switch (job){
    case 0: W = eW0; img = g_wimg_e;                     KIN = 356; Kpad = 384; break;
    case 1: W = eW1; img = g_wimg_e + (size_t)12*8192;   KIN = 256; Kpad = 256; break;
    case 2: W = eW2; img = g_wimg_e + (size_t)20*8192;   KIN = 256; Kpad = 256; break;
    case 3: W = tW0; img = g_wimg_t;                     KIN = 586; Kpad = 640; break;
    case 4: W = tW1; img = g_wimg_t + (size_t)20*8192;   KIN = 256; Kpad = 256; break;
    default:W = tW2; img = g_wimg_t + (size_t)28*8192;   KIN = 256; Kpad = 256; break;
  }
  int gid = blockIdx.x * blockDim.x + threadIdx.x;
  if (gid >= Kpad * 256) return;
  int k = gid >> 8, n = gid & 255;
  float x = (k < KIN) ? W[k * 256 + n] : 0.0f;
  __half hb = __float2half_rn(x);
  int c = k >> 5, kin = k & 31;
  int idx16 = kin * 256 + (((n >> 3) ^ (kin & 7)) << 3) + (n & 7);
  img[(size_t)c * 8192 + idx16] = *(unsigned short*)&hb;
}

// ---------------- fused MLP body ----------------
// NU0 = # of 32-k units for layer0 (edges 12, trip 20)
template<bool TRIP, int KGATH, int NU0>
__device__ __forceinline__ void mlp_body(int bid,
        const float* __restrict__ h,
        const int* __restrict__ i0, const int* __restrict__ i1, const int* __restrict__ i2,
        const float* __restrict__ rn0g, const float* __restrict__ rn1g,
        const float* __restrict__ cvg, const float* __restrict__ svg,
        const float* __restrict__ mug,
        const float* __restrict__ w3g, const float* __restrict__ b3g,
        const unsigned short* __restrict__ wimg,
        float* __restrict__ out, unsigned char* sm, uint32_t sb)
{
  const int tid = threadIdx.x, lane = tid & 31, wid = tid >> 5;
  const int wm = wid & 1, wn = wid >> 1;     // 2 x 4 warp grid over 64 x 256
  const int m15 = wm*32 + (lane & 15);
  const int row0 = bid * TILE_M;

  float* w3s = (float*)(sm + OFF_W3);
  float* b3s = (float*)(sm + OFF_B3);
  float* mus = (float*)(sm + OFF_MU);
  int*   idxs = (int*)(sm + OFF_IDX);
  float* rns = (float*)(sm + OFF_RN);
  float* css = (float*)(sm + OFF_CS);
  float* sss = (float*)(sm + OFF_SS);

  if (tid < 64){
    idxs[tid]      = i0[row0 + tid];
    idxs[64 + tid] = i1[row0 + tid];
    rns[tid]       = rn0g[row0 + tid];
    if (TRIP){
      idxs[128 + tid] = i2[row0 + tid];
      rns[64 + tid]   = rn1g[row0 + tid];
      css[tid]        = cvg[row0 + tid];
      sss[tid]        = svg[row0 + tid];
    }
  }
  if (tid >= 128 && tid < 228) mus[tid - 128] = mug[tid - 128];
  for (int i = tid; i < 768; i += NTH) w3s[i] = w3g[i];
  if (tid < 3) b3s[tid] = b3g[tid];
  __syncthreads();

  float acc[2][8][4];

  auto feat = [&](int k, int r) -> float {
    if (!TRIP){
      int b = k - 256;
      if ((unsigned)b < 100u){ float d = mus[b] - rns[r]; return __expf(-10.0f * d * d); }
      return 0.0f;
    } else {
      if (k < 484){
        int b = k - 384;
        if (b >= 0 && b < 100){ float d = mus[b] - rns[r]; return __expf(-10.0f * d * d); }
        return 0.0f;
      } else if (k < 584){
        float d = mus[k - 484] - rns[64 + r];
        return __expf(-10.0f * d * d);
      } else if (k == 584) return css[r];
      else if (k == 585)   return sss[r];
      return 0.0f;
    }
  };

  // build layer-0 chunk c (64 rows x 64 k-cols fp16). 4 threads per row,
  // warp covers 8 rows x 256B contiguous gather.
  auto genchunk = [&](int c, int slot){
    const int r = tid >> 2, q = tid & 3;
    const int k0 = c * 64 + q * 16;
    unsigned char* hb = sm + X0_OFF + slot * 8192;
    float4 f[4];
    if (c * 64 < KGATH){
      const float4* src = (const float4*)(h + (size_t)idxs[(c >> 1) * 64 + r] * 128 + (k0 & 127));
      f[0] = src[0]; f[1] = src[1]; f[2] = src[2]; f[3] = src[3];
    } else {
      #pragma unroll
      for (int g = 0; g < 4; g++){
        int kk = k0 + g * 4;
        f[g].x = feat(kk, r);   f[g].y = feat(kk+1, r);
        f[g].z = feat(kk+2, r); f[g].w = feat(kk+3, r);
      }
    }
    #pragma unroll
    for (int hf = 0; hf < 2; hf++){
      uint4 v;
      v.x = pack_h2(f[2*hf].x,   f[2*hf].y);
      v.y = pack_h2(f[2*hf].z,   f[2*hf].w);
      v.z = pack_h2(f[2*hf+1].x, f[2*hf+1].y);
      v.w = pack_h2(f[2*hf+1].z, f[2*hf+1].w);
      const unsigned u = (unsigned)(q * 2 + hf);
      const uint32_t off = (uint32_t)(r * 128 + ((u ^ (unsigned)(r & 7)) << 4));
      *(uint4*)(hb + off) = v;
    }
  };

  // stage one 16KB unit into a ring slot (64B per thread)
  auto stageUnit = [&](const unsigned short* wbase, int u, int slot){
    const char* s = (const char*)wbase + (size_t)u * 16384 + tid * 16;
    uint32_t d = sb + W_BUF + (uint32_t)(slot * 16384) + tid * 16;
    #pragma unroll
    for (int i = 0; i < 4; i++) cp16s(d + i * 4096, s + i * 4096);
    cp_commit();
  };

  // stream nu 32-k units; one barrier per unit; 4-deep ring, slot counter s0;
  // prefetch next layer's first 3 units during the tail.
  auto run_layer = [&](int nu, const unsigned short* wbase, bool isL0,
                       const unsigned short* nextbase, bool prestaged, int s0){
    #pragma unroll
    for (int t = 0; t < 2; t++)
      #pragma unroll
      for (int j = 0; j < 8; j++)
        #pragma unroll
        for (int q = 0; q < 4; q++) acc[t][j][q] = 0.0f;
    if (!prestaged){
      stageUnit(wbase, 0, s0 & 3);
      stageUnit(wbase, 1, (s0 + 1) & 3);
      stageUnit(wbase, 2, (s0 + 2) & 3);
    }
    for (int p = 0; p < nu; p++){
      if (nextbase || p <= nu - 3) cp_wait<2>();
      else if (p == nu - 2)        cp_wait<1>();
      else                         cp_wait<0>();
      __syncthreads();
      const int ps = p + 3;
      if (ps < nu)                       stageUnit(wbase, ps, (s0 + ps) & 3);
      else if (nextbase && ps - nu < 3)  stageUnit(nextbase, ps - nu, (s0 + ps) & 3);
      const uint32_t wB = sb + W_BUF + (uint32_t)(((s0 + p) & 3) * 16384);
      if (isL0){
        const int c = p >> 1;
        if (!(p & 1) && (c + 1) * 2 < nu) genchunk(c + 1, (c + 1) & 1);
        const uint32_t xb = sb + X0_OFF + (uint32_t)((c & 1) * 8192);
        pass_single(acc, xb, 128, (p & 1) * 4, wB, lane, wn, m15);
      } else {
        pass_single(acc, sb + ACT16, 512, p * 4, wB, lane, wn, m15);
      }
    }
  };

  // epilogue: silu(acc) -> fp16 ACT (512B rows, swizzled)
  auto epi_act = [&](){
    #pragma unroll
    for (int t = 0; t < 2; t++){
      #pragma unroll
      for (int j = 0; j < 8; j++){
        const int r  = wm*32 + t*16 + (lane >> 2);
        const int cc = wn*64 + j*8 + (lane & 3) * 2;
        float s0 = silu_f(acc[t][j][0]);
        float s1 = silu_f(acc[t][j][1]);
        float s2 = silu_f(acc[t][j][2]);
        float s3 = silu_f(acc[t][j][3]);
        const uint32_t coff = (uint32_t)(((((unsigned)(cc >> 3)) ^ (unsigned)(r & 7)) << 4) + (cc & 7) * 2);
        *(uint32_t*)(sm + ACT16 + r * 512 + coff) = pack_h2(s0, s1);
        const int r2 = r + 8;
        const uint32_t coff2 = (uint32_t)(((((unsigned)(cc >> 3)) ^ (unsigned)(r2 & 7)) << 4) + (cc & 7) * 2);
        *(uint32_t*)(sm + ACT16 + r2 * 512 + coff2) = pack_h2(s2, s3);
      }
    }
  };

  const unsigned short* w1 = wimg + (size_t)NU0 * 8192;
  const unsigned short* w2 = wimg + (size_t)(NU0 + 8) * 8192;
  int s0 = 0;

  // ---- layer 0 ----
  genchunk(0, 0);
  run_layer(NU0, wimg, true, w1, false, s0);
  s0 = (s0 + NU0) & 3;
  __syncthreads();
  epi_act();
  __syncthreads();
  // ---- layer 1 ----
  run_layer(8, w1, false, w2, true, s0);
  s0 = (s0 + 8) & 3;
  __syncthreads();
  epi_act();
  __syncthreads();
  // ---- layer 2 ----
  run_layer(8, w2, false, (const unsigned short*)0, true, s0);
  __syncthreads();            // ACT/W reads done before F32 overwrite
  {
    float* actf = (float*)(sm + F32BUF);
    #pragma unroll
    for (int t = 0; t < 2; t++){
      #pragma unroll
      for (int j = 0; j < 8; j++){
        const int r  = wm*32 + t*16 + (lane >> 2);
        const int cc = wn*64 + j*8 + (lane & 3) * 2;
        actf[r * 257 + cc]           = silu_f(acc[t][j][0]);
        actf[r * 257 + cc + 1]       = silu_f(acc[t][j][1]);
        actf[(r + 8) * 257 + cc]     = silu_f(acc[t][j][2]);
        actf[(r + 8) * 257 + cc + 1] = silu_f(acc[t][j][3]);
      }
    }
  }
  __syncthreads();
  // ---- layer 3: [64 x 256] @ W3[256 x 3] + b3 ----
  {
    float* part = (float*)(sm + PARTS);
    const float* actf = (const float*)(sm + F32BUF);
    const int r = tid >> 2, q = tid & 3;
    float a0 = 0.f, a1 = 0.f, a2 = 0.f;
    const int k0 = q * 64;
    #pragma unroll 16
    for (int k = k0; k < k0 + 64; k++){
      float v = actf[r * 257 + k];
      a0 = fmaf(v, w3s[k * 3 + 0], a0);
      a1 = fmaf(v, w3s[k * 3 + 1], a1);
      a2 = fmaf(v, w3s[k * 3 + 2], a2);
    }
    part[(r * 4 + q) * 3 + 0] = a0;
    part[(r * 4 + q) * 3 + 1] = a1;
    part[(r * 4 + q) * 3 + 2] = a2;
    __syncthreads();
    if (tid < 192){
      const int rr = tid / 3, o = tid - rr * 3;
      float s = b3s[o]
              + part[(rr * 4 + 0) * 3 + o] + part[(rr * 4 + 1) * 3 + o]
              + part[(rr * 4 + 2) * 3 + o] + part[(rr * 4 + 3) * 3 + o];
      out[(size_t)(row0 + rr) * 3 + o] = s;
    }
  }
}

__global__ void __launch_bounds__(NTH, 2)
mlp_all(const float* __restrict__ h,
        const int* __restrict__ src, const int* __restrict__ dst,
        const float* __restrict__ enorm,
        const int* __restrict__ tsrc, const int* __restrict__ tdi, const int* __restrict__ tdj,
        const float* __restrict__ nij, const float* __restrict__ nik,
        const float* __restrict__ cosv, const float* __restrict__ sinv,
        const float* __restrict__ mu,
        const float* __restrict__ eW3, const float* __restrict__ eb3,
        const float* __restrict__ tW3, const float* __restrict__ tb3,
        float* __restrict__ out)
{
  extern __shared__ __align__(1024) unsigned char sm[];
  const uint32_t sb = smem_u32(sm);
  const int bid = blockIdx.x;
  if (bid < NBLK_E){
    mlp_body<false, 256, 12>(bid, h, src, dst, dst, enorm, enorm, enorm, enorm, mu,
                             eW3, eb3, (const unsigned short*)g_wimg_e, out, sm, sb);
  } else {
    mlp_body<true, 384, 20>(bid - NBLK_E, h, tsrc, tdi, tdj, nij, nik, cosv, sinv, mu,
                            tW3, tb3, (const unsigned short*)g_wimg_t,
                            out + (size_t)NEDGE * 3, sm, sb);
  }
}

extern "C" void kernel_launch(void* const* d_in, const int* in_sizes, int n_in,
                              void* d_out, int out_size){
  const float* h     = (const float*)d_in[0];
  const int*   src   = (const int*)  d_in[1];
  const int*   dst   = (const int*)  d_in[2];
  const float* enorm = (const float*)d_in[3];
  const int*   tsrc  = (const int*)  d_in[4];
  const int*   tdi   = (const int*)  d_in[5];
  const int*   tdj   = (const int*)  d_in[6];
  const float* nij   = (const float*)d_in[7];
  const float* nik   = (const float*)d_in[8];
  const float* cosv  = (const float*)d_in[9];
  const float* sinv  = (const float*)d_in[10];
  const float* mu    = (const float*)d_in[11];
  const float* eW0   = (const float*)d_in[12];
  const float* eW1   = (const float*)d_in[13];
  const float* eW2   = (const float*)d_in[14];
  const float* eW3   = (const float*)d_in[15];
  const float* eb3   = (const float*)d_in[16];
  const float* tW0   = (const float*)d_in[17];
  const float* tW1   = (const float*)d_in[18];
  const float* tW2   = (const float*)d_in[19];
  const float* tW3   = (const float*)d_in[20];
  const float* tb3   = (const float*)d_in[21];
  float* out = (float*)d_out;

  prep_all<<<dim3(640, 6), 256>>>(eW0, eW1, eW2, tW0, tW1, tW2);

  cudaFuncSetAttribute(mlp_all, cudaFuncAttributeMaxDynamicSharedMemorySize, SMEM_TOTAL);
  mlp_all<<<NBLK_E + NBLK_T, NTH, SMEM_TOTAL>>>(
      h, src, dst, enorm, tsrc, tdi, tdj, nij, nik, cosv, sinv, mu,
      eW3, eb3, tW3, tb3, out);
}

// round 10
// speedup vs baseline: 5.0455x; 1.0044x over previous
#include <cuda_runtime.h>
#include <cuda_fp16.h>
#include <stdint.h>

#define NEDGE 262144
#define NTRI  393216
#define TILE_M 128
#define NTH   256
#define NBLK_E (NEDGE/TILE_M)   // 2048
#define NBLK_T (NTRI/TILE_M)    // 3072

// ---- smem byte offsets ----
#define W_BUF   0            // 4 slots x 16384 = 65536
#define ACT16   65536        // 65536 (128 rows x 512B fp16)
#define X0_OFF  65536        // 2 slots x 16384 (layer0 ring; overlaps ACT, dead after L0)
#define L3RED   65536        // 128*12 floats = 6144B (after ACT dead)
#define MISC    131072
#define OFF_W3  (MISC)        // 768 floats
#define OFF_B3  (MISC+3072)
#define OFF_MU  (MISC+3088)   // 100 floats
#define OFF_IDX (MISC+3504)   // 3*128 ints
#define OFF_RN  (MISC+5040)   // 2*128 floats
#define OFF_CS  (MISC+6064)
#define OFF_SS  (MISC+6576)
#define SMEM_TOTAL (MISC+7168)   // 138240 -> 1 CTA/SM (8 warps)

// weight images: units of 32k x 256n fp16 (8192 u16 = 16KB).
// edges: L0 12 units @0, L1 8 @12, L2 8 @20.  trip: L0 20 @0, L1 8 @20, L2 8 @28.
__device__ __align__(16) unsigned short g_wimg_e[229376]; // 28 units
__device__ __align__(16) unsigned short g_wimg_t[294912]; // 36 units

__device__ __forceinline__ uint32_t smem_u32(const void* p){
  uint32_t a;
  asm("{ .reg .u64 t; cvta.to.shared.u64 t, %1; cvt.u32.u64 %0, t; }" : "=r"(a) : "l"(p));
  return a;
}
__device__ __forceinline__ void cp16s(uint32_t dst, const void* src){
  asm volatile("cp.async.cg.shared.global [%0], [%1], 16;" :: "r"(dst), "l"(src) : "memory");
}
__device__ __forceinline__ void cp_commit(){ asm volatile("cp.async.commit_group;" ::: "memory"); }
template<int N> __device__ __forceinline__ void cp_wait(){ asm volatile("cp.async.wait_group %0;" :: "n"(N) : "memory"); }

__device__ __forceinline__ void ldsm4(uint32_t (&r)[4], uint32_t a){
  asm volatile("ldmatrix.sync.aligned.m8n8.x4.shared.b16 {%0,%1,%2,%3}, [%4];"
    : "=r"(r[0]), "=r"(r[1]), "=r"(r[2]), "=r"(r[3]) : "r"(a));
}
__device__ __forceinline__ void ldsm4t(uint32_t (&r)[4], uint32_t a){
  asm volatile("ldmatrix.sync.aligned.m8n8.x4.trans.shared.b16 {%0,%1,%2,%3}, [%4];"
    : "=r"(r[0]), "=r"(r[1]), "=r"(r[2]), "=r"(r[3]) : "r"(a));
}
__device__ __forceinline__ void mma_fp(float (&d)[4], const uint32_t (&a)[4], uint32_t b0, uint32_t b1){
  asm volatile("mma.sync.aligned.m16n8k16.row.col.f32.f16.f16.f32 "
    "{%0,%1,%2,%3}, {%4,%5,%6,%7}, {%8,%9}, {%0,%1,%2,%3};"
    : "+f"(d[0]), "+f"(d[1]), "+f"(d[2]), "+f"(d[3])
    : "r"(a[0]), "r"(a[1]), "r"(a[2]), "r"(a[3]), "r"(b0), "r"(b1));
}

__device__ __forceinline__ uint32_t pack_h2(float x, float y){
  __half2 t = __floats2half2_rn(x, y);
  return *(uint32_t*)&t;
}
__device__ __forceinline__ float silu_f(float x){
  return __fdividef(x, 1.0f + __expf(-x));
}

// One 32-k unit, warp tile 64m x 64n: 8 LDSM + 64 HMMA (1.0 wf/HMMA from LDSM).
__device__ __forceinline__ void pass_single(float (&acc)[4][8][4],
    uint32_t aB, int aRB, int kub, uint32_t wB, int lane, int wn, int wm){
  #pragma unroll
  for (int ks = 0; ks < 2; ks++){
    const int ku = kub + ks*2 + (lane >> 4);
    const uint32_t sw = (uint32_t)((ku ^ (lane & 7)) << 4);
    uint32_t afr[4][4];
    #pragma unroll
    for (int mb = 0; mb < 4; mb++)
      ldsm4(afr[mb], aB + (uint32_t)((wm*64 + mb*16 + (lane & 15)) * aRB) + sw);
    const uint32_t wro = (uint32_t)((ks*16 + (lane & 15)) * 512);
    #pragma unroll
    for (int jj = 0; jj < 4; jj++){
      const int nu = wn*8 + jj*2 + (lane >> 4);
      const uint32_t nsw = (uint32_t)((nu ^ (lane & 7)) << 4);
      uint32_t b[4];
      ldsm4t(b, wB + wro + nsw);
      #pragma unroll
      for (int mb = 0; mb < 4; mb++){
        mma_fp(acc[mb][2*jj],   afr[mb], b[0], b[1]);
        mma_fp(acc[mb][2*jj+1], afr[mb], b[2], b[3]);
      }
    }
  }
}

// ---- weight prep: all 6 matrices, fp16, pre-swizzled 16KB units ----
__global__ void prep_all(const float* __restrict__ eW0, const float* __restrict__ eW1,
                         const float* __restrict__ eW2, const float* __restrict__ tW0,
                         const float* __restrict__ tW1, const float* __restrict__ tW2){
  const int job = blockIdx.y;
  const float* W; unsigned short* img; int KIN, Kpad;
  switch (job){
    case 0: W = eW0; img = g_wimg_e;                     KIN = 356; Kpad = 384; break;
    case 1: W = eW1; img = g_wimg_e + (size_t)12*8192;   KIN = 256; Kpad = 256; break;
    case 2: W = eW2; img = g_wimg_e + (size_t)20*8192;   KIN = 256; Kpad = 256; break;
    case 3: W = tW0; img = g_wimg_t;                     KIN = 586; Kpad = 640; break;
    case 4: W = tW1; img = g_wimg_t + (size_t)20*8192;   KIN = 256; Kpad = 256; break;
    default:W = tW2; img = g_wimg_t + (size_t)28*8192;   KIN = 256; Kpad = 256; break;
  }
  int gid = blockIdx.x * blockDim.x + threadIdx.x;
  if (gid >= Kpad * 256) return;
  int k = gid >> 8, n = gid & 255;
  float x = (k < KIN) ? W[k * 256 + n] : 0.0f;
  __half hb = __float2half_rn(x);
  int c = k >> 5, kin = k & 31;
  int idx16 = kin * 256 + (((n >> 3) ^ (kin & 7)) << 3) + (n & 7);
  img[(size_t)c * 8192 + idx16] = *(unsigned short*)&hb;
}

// ---------------- fused MLP body ----------------
// NU0 = # of 32-k units for layer0 (edges 12, trip 20)
template<bool TRIP, int KGATH, int NU0>
__device__ __forceinline__ void mlp_body(int bid,
        const float* __restrict__ h,
        const int* __restrict__ i0, const int* __restrict__ i1, const int* __restrict__ i2,
        const float* __restrict__ rn0g, const float* __restrict__ rn1g,
        const float* __restrict__ cvg, const float* __restrict__ svg,
        const float* __restrict__ mug,
        const float* __restrict__ w3g, const float* __restrict__ b3g,
        const unsigned short* __restrict__ wimg,
        float* __restrict__ out, unsigned char* sm, uint32_t sb)
{
  const int tid = threadIdx.x, lane = tid & 31, wid = tid >> 5;
  const int wm = wid & 1, wn = wid >> 1;     // 2 x 4 warp grid over 128 x 256
  const int row0 = bid * TILE_M;

  float* w3s = (float*)(sm + OFF_W3);
  float* b3s = (float*)(sm + OFF_B3);
  float* mus = (float*)(sm + OFF_MU);
  int*   idxs = (int*)(sm + OFF_IDX);
  float* rns = (float*)(sm + OFF_RN);
  float* css = (float*)(sm + OFF_CS);
  float* sss = (float*)(sm + OFF_SS);

  if (tid < 128){
    idxs[tid]       = i0[row0 + tid];
    idxs[128 + tid] = i1[row0 + tid];
    rns[tid]        = rn0g[row0 + tid];
    if (TRIP){
      idxs[256 + tid] = i2[row0 + tid];
      rns[128 + tid]  = rn1g[row0 + tid];
      css[tid]        = cvg[row0 + tid];
      sss[tid]        = svg[row0 + tid];
    }
  } else if (tid < 228){
    mus[tid - 128] = mug[tid - 128];
  }
  for (int i = tid; i < 768; i += NTH) w3s[i] = w3g[i];
  if (tid < 3) b3s[tid] = b3g[tid];
  __syncthreads();

  float acc[4][8][4];

  auto feat = [&](int k, int r) -> float {
    if (!TRIP){
      int b = k - 256;
      if ((unsigned)b < 100u){ float d = mus[b] - rns[r]; return __expf(-10.0f * d * d); }
      return 0.0f;
    } else {
      if (k < 484){
        int b = k - 384;
        if (b >= 0 && b < 100){ float d = mus[b] - rns[r]; return __expf(-10.0f * d * d); }
        return 0.0f;
      } else if (k < 584){
        float d = mus[k - 484] - rns[128 + r];
        return __expf(-10.0f * d * d);
      } else if (k == 584) return css[r];
      else if (k == 585)   return sss[r];
      return 0.0f;
    }
  };

  // build layer-0 chunk c (128 rows x 64 k-cols fp16). 2 threads per row,
  // each thread 32 k-cols (128B contiguous gather).
  auto genchunk = [&](int c, int slot){
    const int r = tid >> 1, q = tid & 1;
    const int k0 = c * 64 + q * 32;
    unsigned char* hb = sm + X0_OFF + slot * 16384;
    float4 f[8];
    if (c * 64 < KGATH){
      const float4* src = (const float4*)(h + (size_t)idxs[(c >> 1) * 128 + r] * 128 + (k0 & 127));
      #pragma unroll
      for (int g = 0; g < 8; g++) f[g] = src[g];
    } else {
      #pragma unroll
      for (int g = 0; g < 8; g++){
        int kk = k0 + g * 4;
        f[g].x = feat(kk, r);   f[g].y = feat(kk+1, r);
        f[g].z = feat(kk+2, r); f[g].w = feat(kk+3, r);
      }
    }
    #pragma unroll
    for (int hf = 0; hf < 4; hf++){
      uint4 v;
      v.x = pack_h2(f[2*hf].x,   f[2*hf].y);
      v.y = pack_h2(f[2*hf].z,   f[2*hf].w);
      v.z = pack_h2(f[2*hf+1].x, f[2*hf+1].y);
      v.w = pack_h2(f[2*hf+1].z, f[2*hf+1].w);
      const unsigned u = (unsigned)(q * 4 + hf);
      const uint32_t off = (uint32_t)(r * 128 + ((u ^ (unsigned)(r & 7)) << 4));
      *(uint4*)(hb + off) = v;
    }
  };

  // stage one 16KB unit into a ring slot (64B per thread)
  auto stageUnit = [&](const unsigned short* wbase, int u, int slot){
    const char* s = (const char*)wbase + (size_t)u * 16384 + tid * 16;
    uint32_t d = sb + W_BUF + (uint32_t)(slot * 16384) + tid * 16;
    #pragma unroll
    for (int i = 0; i < 4; i++) cp16s(d + i * 4096, s + i * 4096);
    cp_commit();
  };

  // stream nu 32-k units; one barrier per unit; 4-deep ring, slot counter s0;
  // prefetch next layer's first 3 units during the tail.
  auto run_layer = [&](int nu, const unsigned short* wbase, bool isL0,
                       const unsigned short* nextbase, bool prestaged, int s0){
    #pragma unroll
    for (int t = 0; t < 4; t++)
      #pragma unroll
      for (int j = 0; j < 8; j++)
        #pragma unroll
        for (int q = 0; q < 4; q++) acc[t][j][q] = 0.0f;
    if (!prestaged){
      stageUnit(wbase, 0, s0 & 3);
      stageUnit(wbase, 1, (s0 + 1) & 3);
      stageUnit(wbase, 2, (s0 + 2) & 3);
    }
    for (int p = 0; p < nu; p++){
      if (nextbase || p <= nu - 3) cp_wait<2>();
      else if (p == nu - 2)        cp_wait<1>();
      else                         cp_wait<0>();
      __syncthreads();
      const int ps = p + 3;
      if (ps < nu)                       stageUnit(wbase, ps, (s0 + ps) & 3);
      else if (nextbase && ps - nu < 3)  stageUnit(nextbase, ps - nu, (s0 + ps) & 3);
      const uint32_t wB = sb + W_BUF + (uint32_t)(((s0 + p) & 3) * 16384);
      if (isL0){
        const int c = p >> 1;
        if (!(p & 1) && (c + 1) * 2 < nu) genchunk(c + 1, (c + 1) & 1);
        const uint32_t xb = sb + X0_OFF + (uint32_t)((c & 1) * 16384);
        pass_single(acc, xb, 128, (p & 1) * 4, wB, lane, wn, wm);
      } else {
        pass_single(acc, sb + ACT16, 512, p * 4, wB, lane, wn, wm);
      }
    }
  };

  // epilogue: silu(acc) -> fp16 ACT (512B rows, swizzled)
  auto epi_act = [&](){
    #pragma unroll
    for (int t = 0; t < 4; t++){
      #pragma unroll
      for (int j = 0; j < 8; j++){
        const int r  = wm*64 + t*16 + (lane >> 2);
        const int cc = wn*64 + j*8 + (lane & 3) * 2;
        float s0 = silu_f(acc[t][j][0]);
        float s1 = silu_f(acc[t][j][1]);
        float s2 = silu_f(acc[t][j][2]);
        float s3 = silu_f(acc[t][j][3]);
        const uint32_t coff = (uint32_t)(((((unsigned)(cc >> 3)) ^ (unsigned)(r & 7)) << 4) + (cc & 7) * 2);
        *(uint32_t*)(sm + ACT16 + r * 512 + coff) = pack_h2(s0, s1);
        const int r2 = r + 8;
        const uint32_t coff2 = (uint32_t)(((((unsigned)(cc >> 3)) ^ (unsigned)(r2 & 7)) << 4) + (cc & 7) * 2);
        *(uint32_t*)(sm + ACT16 + r2 * 512 + coff2) = pack_h2(s2, s3);
      }
    }
  };

  const unsigned short* w1 = wimg + (size_t)NU0 * 8192;
  const unsigned short* w2 = wimg + (size_t)(NU0 + 8) * 8192;
  int s0 = 0;

  // ---- layer 0 ----
  genchunk(0, 0);
  run_layer(NU0, wimg, true, w1, false, s0);
  s0 = (s0 + NU0) & 3;
  __syncthreads();
  epi_act();
  __syncthreads();
  // ---- layer 1 ----
  run_layer(8, w1, false, w2, true, s0);
  s0 = (s0 + 8) & 3;
  __syncthreads();
  epi_act();
  __syncthreads();
  // ---- layer 2 ----
  run_layer(8, w2, false, (const unsigned short*)0, true, s0);
  __syncthreads();            // ACT reads done before L3RED overwrite
  // ---- layer 3: silu(acc) @ W3 directly from registers ----
  {
    float* red = (float*)(sm + L3RED);
    #pragma unroll
    for (int t = 0; t < 4; t++){
      #pragma unroll
      for (int half = 0; half < 2; half++){
        float p0 = 0.f, p1 = 0.f, p2 = 0.f;
        #pragma unroll
        for (int j = 0; j < 8; j++){
          #pragma unroll
          for (int b = 0; b < 2; b++){
            const int c = wn*64 + j*8 + (lane & 3) * 2 + b;
            float v = silu_f(acc[t][j][half*2 + b]);
            p0 = fmaf(v, w3s[c*3 + 0], p0);
            p1 = fmaf(v, w3s[c*3 + 1], p1);
            p2 = fmaf(v, w3s[c*3 + 2], p2);
          }
        }
        p0 += __shfl_xor_sync(0xFFFFFFFFu, p0, 1);
        p0 += __shfl_xor_sync(0xFFFFFFFFu, p0, 2);
        p1 += __shfl_xor_sync(0xFFFFFFFFu, p1, 1);
        p1 += __shfl_xor_sync(0xFFFFFFFFu, p1, 2);
        p2 += __shfl_xor_sync(0xFFFFFFFFu, p2, 1);
        p2 += __shfl_xor_sync(0xFFFFFFFFu, p2, 2);
        if ((lane & 3) == 0){
          const int row = wm*64 + t*16 + (lane >> 2) + half*8;
          red[row*12 + wn*3 + 0] = p0;
          red[row*12 + wn*3 + 1] = p1;
          red[row*12 + wn*3 + 2] = p2;
        }
      }
    }
    __syncthreads();
    for (int i = tid; i < 128*3; i += NTH){
      const int row = i / 3, o = i - row*3;
      float s = b3s[o] + red[row*12 + o] + red[row*12 + 3 + o]
              + red[row*12 + 6 + o] + red[row*12 + 9 + o];
      out[(size_t)(row0 + row) * 3 + o] = s;
    }
  }
}

__global__ void __launch_bounds__(NTH, 1)
mlp_all(const float* __restrict__ h,
        const int* __restrict__ src, const int* __restrict__ dst,
        const float* __restrict__ enorm,
        const int* __restrict__ tsrc, const int* __restrict__ tdi, const int* __restrict__ tdj,
        const float* __restrict__ nij, const float* __restrict__ nik,
        const float* __restrict__ cosv, const float* __restrict__ sinv,
        const float* __restrict__ mu,
        const float* __restrict__ eW3, const float* __restrict__ eb3,
        const float* __restrict__ tW3, const float* __restrict__ tb3,
        float* __restrict__ out)
{
  extern __shared__ __align__(1024) unsigned char sm[];
  const uint32_t sb = smem_u32(sm);
  const int bid = blockIdx.x;
  if (bid < NBLK_E){
    mlp_body<false, 256, 12>(bid, h, src, dst, dst, enorm, enorm, enorm, enorm, mu,
                             eW3, eb3, (const unsigned short*)g_wimg_e, out, sm, sb);
  } else {
    mlp_body<true, 384, 20>(bid - NBLK_E, h, tsrc, tdi, tdj, nij, nik, cosv, sinv, mu,
                            tW3, tb3, (const unsigned short*)g_wimg_t,
                            out + (size_t)NEDGE * 3, sm, sb);
  }
}

extern "C" void kernel_launch(void* const* d_in, const int* in_sizes, int n_in,
                              void* d_out, int out_size){
  const float* h     = (const float*)d_in[0];
  const int*   src   = (const int*)  d_in[1];
  const int*   dst   = (const int*)  d_in[2];
  const float* enorm = (const float*)d_in[3];
  const int*   tsrc  = (const int*)  d_in[4];
  const int*   tdi   = (const int*)  d_in[5];
  const int*   tdj   = (const int*)  d_in[6];
  const float* nij   = (const float*)d_in[7];
  const float* nik   = (const float*)d_in[8];
  const float* cosv  = (const float*)d_in[9];
  const float* sinv  = (const float*)d_in[10];
  const float* mu    = (const float*)d_in[11];
  const float* eW0   = (const float*)d_in[12];
  const float* eW1   = (const float*)d_in[13];
  const float* eW2   = (const float*)d_in[14];
  const float* eW3   = (const float*)d_in[15];
  const float* eb3   = (const float*)d_in[16];
  const float* tW0   = (const float*)d_in[17];
  const float* tW1   = (const float*)d_in[18];
  const float* tW2   = (const float*)d_in[19];
  const float* tW3   = (const float*)d_in[20];
  const float* tb3   = (const float*)d_in[21];
  float* out = (float*)d_out;

  prep_all<<<dim3(640, 6), 256>>>(eW0, eW1, eW2, tW0, tW1, tW2);

  cudaFuncSetAttribute(mlp_all, cudaFuncAttributeMaxDynamicSharedMemorySize, SMEM_TOTAL);
  mlp_all<<<NBLK_E + NBLK_T, NTH, SMEM_TOTAL>>>(
      h, src, dst, enorm, tsrc, tdi, tdj, nij, nik, cosv, sinv, mu,
      eW3, eb3, tW3, tb3, out);
}

// round 12
// speedup vs baseline: 6.1861x; 1.2261x over previous
#include <cuda_runtime.h>
#include <cuda_fp16.h>
#include <stdint.h>

#define NEDGE 262144
#define NTRI  393216
#define TILE_M 128
#define NTH   512
#define NBLK_E (NEDGE/TILE_M)   // 2048
#define NBLK_T (NTRI/TILE_M)    // 3072

// ---- smem byte offsets ----
#define ACT16   0            // 65536 (128 rows x 512B fp16)
#define X0_OFF  0            // 2 slots x 16384 inside ACT16 (dead after L0)
#define L3RED   65536        // 128*24 floats = 12288
#define MISC    81920
#define OFF_W3  (MISC)        // 768 floats
#define OFF_B3  (MISC+3072)
#define OFF_MU  (MISC+3088)   // 100 floats
#define OFF_IDX (MISC+3504)   // 3*128 ints
#define OFF_RN  (MISC+5040)   // 2*128 floats
#define OFF_CS  (MISC+6064)
#define OFF_SS  (MISC+6576)
#define SMEM_TOTAL (MISC+7168)   // 89088

// W fragment images: per 32-k unit: 2 ks x 16 npair x 32 lanes x uint4.
// Frag content follows PTX m16n8k16 B layout (k=2*(l%4)+i, n=l/4 per 8x8 block).
// edges: L0 12 units, L1 8, L2 8 (28). trip: 20+8+8 (36). Units contiguous.
__device__ __align__(16) uint4 g_wfrag_e[28672];  // 28*1024
__device__ __align__(16) uint4 g_wfrag_t[36864];  // 36*1024

__device__ __forceinline__ uint32_t smem_u32(const void* p){
  uint32_t a;
  asm("{ .reg .u64 t; cvta.to.shared.u64 t, %1; cvt.u32.u64 %0, t; }" : "=r"(a) : "l"(p));
  return a;
}
__device__ __forceinline__ void ldsm4(uint32_t (&r)[4], uint32_t a){
  asm volatile("ldmatrix.sync.aligned.m8n8.x4.shared.b16 {%0,%1,%2,%3}, [%4];"
    : "=r"(r[0]), "=r"(r[1]), "=r"(r[2]), "=r"(r[3]) : "r"(a));
}
__device__ __forceinline__ void mma_fp(float (&d)[4], const uint32_t (&a)[4], uint32_t b0, uint32_t b1){
  asm volatile("mma.sync.aligned.m16n8k16.row.col.f32.f16.f16.f32 "
    "{%0,%1,%2,%3}, {%4,%5,%6,%7}, {%8,%9}, {%0,%1,%2,%3};"
    : "+f"(d[0]), "+f"(d[1]), "+f"(d[2]), "+f"(d[3])
    : "r"(a[0]), "r"(a[1]), "r"(a[2]), "r"(a[3]), "r"(b0), "r"(b1));
}
__device__ __forceinline__ uint32_t pack_h2(float x, float y){
  __half2 t = __floats2half2_rn(x, y);
  return *(uint32_t*)&t;
}
__device__ __forceinline__ float silu_f(float x){
  return __fdividef(x, 1.0f + __expf(-x));
}

// ---- prep: write W as PTX B-fragments, one uint4 per (unit,ks,npair,lane) ----
__global__ void prep_frag(const float* __restrict__ eW0, const float* __restrict__ eW1,
                          const float* __restrict__ eW2, const float* __restrict__ tW0,
                          const float* __restrict__ tW1, const float* __restrict__ tW2){
  const int job = blockIdx.y;
  const float* W; uint4* img; int KIN, NU;
  switch (job){
    case 0: W = eW0; img = g_wfrag_e;         KIN = 356; NU = 12; break;
    case 1: W = eW1; img = g_wfrag_e + 12288; KIN = 256; NU = 8;  break;
    case 2: W = eW2; img = g_wfrag_e + 20480; KIN = 256; NU = 8;  break;
    case 3: W = tW0; img = g_wfrag_t;         KIN = 586; NU = 20; break;
    case 4: W = tW1; img = g_wfrag_t + 20480; KIN = 256; NU = 8;  break;
    default:W = tW2; img = g_wfrag_t + 28672; KIN = 256; NU = 8;  break;
  }
  int gid = blockIdx.x * blockDim.x + threadIdx.x;
  if (gid >= NU * 1024) return;
  const int u  = gid >> 10;
  const int ks = (gid >> 9) & 1;
  const int p  = (gid >> 5) & 15;
  const int l  = gid & 31;
  const int kw = u * 32 + ks * 16 + (l & 3) * 2;   // k rows kw, kw+1 (b0); +8 (b1)
  const int na = p * 16 + (l >> 2);                // n of first 8-block
  const int nb = na + 8;
  auto get = [&](int k, int n) -> float { return (k < KIN) ? W[k * 256 + n] : 0.0f; };
  uint4 v;
  v.x = pack_h2(get(kw,     na), get(kw + 1, na));
  v.y = pack_h2(get(kw + 8, na), get(kw + 9, na));
  v.z = pack_h2(get(kw,     nb), get(kw + 1, nb));
  v.w = pack_h2(get(kw + 8, nb), get(kw + 9, nb));
  img[gid] = v;
}

// ---------------- fused MLP body ----------------
// NU0 = # of 32-k units for layer0 (edges 12, trip 20); total units NU0+16.
template<bool TRIP, int KGATH, int NU0>
__device__ __forceinline__ void mlp_body(int bid,
        const float* __restrict__ h,
        const int* __restrict__ i0, const int* __restrict__ i1, const int* __restrict__ i2,
        const float* __restrict__ rn0g, const float* __restrict__ rn1g,
        const float* __restrict__ cvg, const float* __restrict__ svg,
        const float* __restrict__ mug,
        const float* __restrict__ w3g, const float* __restrict__ b3g,
        const uint4* __restrict__ wfrag,
        float* __restrict__ out, unsigned char* sm, uint32_t sb)
{
  const int tid = threadIdx.x, lane = tid & 31, wid = tid >> 5;
  const int wm = wid & 1, wn = wid >> 1;     // 2m x 8n grid, warp tile 64x32
  const int row0 = bid * TILE_M;
  const int NUTOT = NU0 + 16;

  float* w3s = (float*)(sm + OFF_W3);
  float* b3s = (float*)(sm + OFF_B3);
  float* mus = (float*)(sm + OFF_MU);
  int*   idxs = (int*)(sm + OFF_IDX);
  float* rns = (float*)(sm + OFF_RN);
  float* css = (float*)(sm + OFF_CS);
  float* sss = (float*)(sm + OFF_SS);

  if (tid < 128){
    idxs[tid]       = i0[row0 + tid];
    idxs[128 + tid] = i1[row0 + tid];
    rns[tid]        = rn0g[row0 + tid];
    if (TRIP){
      idxs[256 + tid] = i2[row0 + tid];
      rns[128 + tid]  = rn1g[row0 + tid];
      css[tid]        = cvg[row0 + tid];
      sss[tid]        = svg[row0 + tid];
    }
  } else if (tid < 228){
    mus[tid - 128] = mug[tid - 128];
  }
  for (int i = tid; i < 768; i += NTH) w3s[i] = w3g[i];
  if (tid < 3) b3s[tid] = b3g[tid];
  __syncthreads();   // idxs/rns/mus visible to ALL threads before genchunk(0)

  float acc[4][4][4];   // [m-block][n8][frag]

  auto feat = [&](int k, int r) -> float {
    if (!TRIP){
      int b = k - 256;
      if ((unsigned)b < 100u){ float d = mus[b] - rns[r]; return __expf(-10.0f * d * d); }
      return 0.0f;
    } else {
      if (k < 484){
        int b = k - 384;
        if (b >= 0 && b < 100){ float d = mus[b] - rns[r]; return __expf(-10.0f * d * d); }
        return 0.0f;
      } else if (k < 584){
        float d = mus[k - 484] - rns[128 + r];
        return __expf(-10.0f * d * d);
      } else if (k == 584) return css[r];
      else if (k == 585)   return sss[r];
      return 0.0f;
    }
  };

  // layer-0 chunk c: 128 rows x 64 k-cols fp16 (4 threads/row, 16 cols each)
  auto genchunk = [&](int c, int slot){
    const int r = tid >> 2, q = tid & 3;
    const int k0 = c * 64 + q * 16;
    unsigned char* hb = sm + X0_OFF + slot * 16384;
    float4 f[4];
    if (c * 64 < KGATH){
      const float4* src = (const float4*)(h + (size_t)idxs[(c >> 1) * 128 + r] * 128 + (k0 & 127));
      f[0] = src[0]; f[1] = src[1]; f[2] = src[2]; f[3] = src[3];
    } else {
      #pragma unroll
      for (int g = 0; g < 4; g++){
        int kk = k0 + g * 4;
        f[g].x = feat(kk, r);   f[g].y = feat(kk+1, r);
        f[g].z = feat(kk+2, r); f[g].w = feat(kk+3, r);
      }
    }
    #pragma unroll
    for (int hf = 0; hf < 2; hf++){
      uint4 v;
      v.x = pack_h2(f[2*hf].x,   f[2*hf].y);
      v.y = pack_h2(f[2*hf].z,   f[2*hf].w);
      v.z = pack_h2(f[2*hf+1].x, f[2*hf+1].y);
      v.w = pack_h2(f[2*hf+1].z, f[2*hf+1].w);
      const unsigned u = (unsigned)(q * 2 + hf);
      const uint32_t off = (uint32_t)(r * 128 + ((u ^ (unsigned)(r & 7)) << 4));
      *(uint4*)(hb + off) = v;
    }
  };

  // load one unit's B frags for this warp (4 LDG.128 from L2-resident image)
  auto loadB = [&](int u, uint4 (&bf)[2][2]){
    #pragma unroll
    for (int ks = 0; ks < 2; ks++)
      #pragma unroll
      for (int jj = 0; jj < 2; jj++)
        bf[ks][jj] = __ldg(&wfrag[(((u*2 + ks)*16) + wn*2 + jj)*32 + lane]);
  };

  // one 32-k unit of MMA: warp tile 64x32, A from smem (verified path), B from regs
  auto mma_unit = [&](uint32_t aB, int aRB, int kub, const uint4 (&bf)[2][2]){
    #pragma unroll
    for (int ks = 0; ks < 2; ks++){
      const int ku = kub + ks*2 + (lane >> 4);
      const uint32_t sw = (uint32_t)((ku ^ (lane & 7)) << 4);
      uint32_t afr[4][4];
      #pragma unroll
      for (int mb = 0; mb < 4; mb++)
        ldsm4(afr[mb], aB + (uint32_t)((wm*64 + mb*16 + (lane & 15)) * aRB) + sw);
      #pragma unroll
      for (int jj = 0; jj < 2; jj++){
        const uint4 b = bf[ks][jj];
        #pragma unroll
        for (int mb = 0; mb < 4; mb++){
          mma_fp(acc[mb][jj*2 + 0], afr[mb], b.x, b.y);
          mma_fp(acc[mb][jj*2 + 1], afr[mb], b.z, b.w);
        }
      }
    }
  };

  auto zero_acc = [&](){
    #pragma unroll
    for (int t = 0; t < 4; t++)
      #pragma unroll
      for (int j = 0; j < 4; j++)
        #pragma unroll
        for (int q = 0; q < 4; q++) acc[t][j][q] = 0.0f;
  };

  // epilogue: silu(acc) -> fp16 ACT (512B rows, swizzled)
  auto epi_act = [&](){
    #pragma unroll
    for (int mb = 0; mb < 4; mb++){
      #pragma unroll
      for (int j = 0; j < 4; j++){
        const int r  = wm*64 + mb*16 + (lane >> 2);
        const int cc = wn*32 + j*8 + (lane & 3) * 2;
        float s0 = silu_f(acc[mb][j][0]);
        float s1 = silu_f(acc[mb][j][1]);
        float s2 = silu_f(acc[mb][j][2]);
        float s3 = silu_f(acc[mb][j][3]);
        const uint32_t coff = (uint32_t)(((((unsigned)(cc >> 3)) ^ (unsigned)(r & 7)) << 4) + (cc & 7) * 2);
        *(uint32_t*)(sm + ACT16 + r * 512 + coff) = pack_h2(s0, s1);
        const int r2 = r + 8;
        const uint32_t coff2 = (uint32_t)(((((unsigned)(cc >> 3)) ^ (unsigned)(r2 & 7)) << 4) + (cc & 7) * 2);
        *(uint32_t*)(sm + ACT16 + r2 * 512 + coff2) = pack_h2(s2, s3);
      }
    }
  };

  uint4 bufA[2][2], bufB[2][2];
  auto clampu = [&](int u){ return u < NUTOT ? u : NUTOT - 1; };

  // ---- layer 0: double-buffered generated A chunks, B prefetched 1 unit ahead ----
  genchunk(0, 0);
  loadB(0, bufA);
  zero_acc();
  const int NC0 = NU0 / 2;
  for (int c = 0; c < NC0; c++){
    __syncthreads();                       // chunk c visible; slot (c+1)&1 free
    if (c + 1 < NC0) genchunk(c + 1, (c + 1) & 1);
    const uint32_t xb = sb + X0_OFF + (uint32_t)((c & 1) * 16384);
    loadB(2*c + 1, bufB);
    mma_unit(xb, 128, 0, bufA);
    loadB(clampu(2*c + 2), bufA);
    mma_unit(xb, 128, 4, bufB);
  }
  __syncthreads();                          // X0 reads done before ACT overwrite
  epi_act();
  __syncthreads();
  // ---- layer 1: barrier-free, bufA holds unit NU0 ----
  zero_acc();
  for (int p = 0; p < 8; p++){
    const int u = NU0 + p;
    if (!(p & 1)){
      loadB(clampu(u + 1), bufB);
      mma_unit(sb + ACT16, 512, p * 4, bufA);
    } else {
      loadB(clampu(u + 1), bufA);
      mma_unit(sb + ACT16, 512, p * 4, bufB);
    }
  }
  __syncthreads();                          // ACT reads done before overwrite
  epi_act();
  __syncthreads();
  // ---- layer 2: barrier-free, bufA holds unit NU0+8 ----
  zero_acc();
  for (int p = 0; p < 8; p++){
    const int u = NU0 + 8 + p;
    if (!(p & 1)){
      loadB(clampu(u + 1), bufB);
      mma_unit(sb + ACT16, 512, p * 4, bufA);
    } else {
      loadB(clampu(u + 1), bufA);
      mma_unit(sb + ACT16, 512, p * 4, bufB);
    }
  }
  // ---- layer 3: silu(acc) @ W3 from registers, shfl + smem reduce ----
  __syncthreads();                          // ACT dead; L3RED region free
  {
    float* red = (float*)(sm + L3RED);      // [row][wn][3]
    #pragma unroll
    for (int mb = 0; mb < 4; mb++){
      #pragma unroll
      for (int half = 0; half < 2; half++){
        float p0 = 0.f, p1 = 0.f, p2 = 0.f;
        #pragma unroll
        for (int j = 0; j < 4; j++){
          #pragma unroll
          for (int b = 0; b < 2; b++){
            const int c = wn*32 + j*8 + (lane & 3) * 2 + b;
            float v = silu_f(acc[mb][j][half*2 + b]);
            p0 = fmaf(v, w3s[c*3 + 0], p0);
            p1 = fmaf(v, w3s[c*3 + 1], p1);
            p2 = fmaf(v, w3s[c*3 + 2], p2);
          }
        }
        p0 += __shfl_xor_sync(0xFFFFFFFFu, p0, 1);
        p0 += __shfl_xor_sync(0xFFFFFFFFu, p0, 2);
        p1 += __shfl_xor_sync(0xFFFFFFFFu, p1, 1);
        p1 += __shfl_xor_sync(0xFFFFFFFFu, p1, 2);
        p2 += __shfl_xor_sync(0xFFFFFFFFu, p2, 1);
        p2 += __shfl_xor_sync(0xFFFFFFFFu, p2, 2);
        if ((lane & 3) == 0){
          const int row = wm*64 + mb*16 + (lane >> 2) + half*8;
          red[row*24 + wn*3 + 0] = p0;
          red[row*24 + wn*3 + 1] = p1;
          red[row*24 + wn*3 + 2] = p2;
        }
      }
    }
    __syncthreads();
    for (int i = tid; i < 128*3; i += NTH){
      const int row = i / 3, o = i - row*3;
      float s = b3s[o];
      #pragma unroll
      for (int w = 0; w < 8; w++) s += red[row*24 + w*3 + o];
      out[(size_t)(row0 + row) * 3 + o] = s;
    }
  }
}

__global__ void __launch_bounds__(NTH, 1)
mlp_all(const float* __restrict__ h,
        const int* __restrict__ src, const int* __restrict__ dst,
        const float* __restrict__ enorm,
        const int* __restrict__ tsrc, const int* __restrict__ tdi, const int* __restrict__ tdj,
        const float* __restrict__ nij, const float* __restrict__ nik,
        const float* __restrict__ cosv, const float* __restrict__ sinv,
        const float* __restrict__ mu,
        const float* __restrict__ eW3, const float* __restrict__ eb3,
        const float* __restrict__ tW3, const float* __restrict__ tb3,
        float* __restrict__ out)
{
  extern __shared__ __align__(1024) unsigned char sm[];
  const uint32_t sb = smem_u32(sm);
  const int bid = blockIdx.x;
  if (bid < NBLK_E){
    mlp_body<false, 256, 12>(bid, h, src, dst, dst, enorm, enorm, enorm, enorm, mu,
                             eW3, eb3, (const uint4*)g_wfrag_e, out, sm, sb);
  } else {
    mlp_body<true, 384, 20>(bid - NBLK_E, h, tsrc, tdi, tdj, nij, nik, cosv, sinv, mu,
                            tW3, tb3, (const uint4*)g_wfrag_t,
                            out + (size_t)NEDGE * 3, sm, sb);
  }
}

extern "C" void kernel_launch(void* const* d_in, const int* in_sizes, int n_in,
                              void* d_out, int out_size){
  const float* h     = (const float*)d_in[0];
  const int*   src   = (const int*)  d_in[1];
  const int*   dst   = (const int*)  d_in[2];
  const float* enorm = (const float*)d_in[3];
  const int*   tsrc  = (const int*)  d_in[4];
  const int*   tdi   = (const int*)  d_in[5];
  const int*   tdj   = (const int*)  d_in[6];
  const float* nij   = (const float*)d_in[7];
  const float* nik   = (const float*)d_in[8];
  const float* cosv  = (const float*)d_in[9];
  const float* sinv  = (const float*)d_in[10];
  const float* mu    = (const float*)d_in[11];
  const float* eW0   = (const float*)d_in[12];
  const float* eW1   = (const float*)d_in[13];
  const float* eW2   = (const float*)d_in[14];
  const float* eW3   = (const float*)d_in[15];
  const float* eb3   = (const float*)d_in[16];
  const float* tW0   = (const float*)d_in[17];
  const float* tW1   = (const float*)d_in[18];
  const float* tW2   = (const float*)d_in[19];
  const float* tW3   = (const float*)d_in[20];
  const float* tb3   = (const float*)d_in[21];
  float* out = (float*)d_out;

  // 20 units * 1024 = 20480 max elements per job
  prep_frag<<<dim3(80, 6), 256>>>(eW0, eW1, eW2, tW0, tW1, tW2);

  cudaFuncSetAttribute(mlp_all, cudaFuncAttributeMaxDynamicSharedMemorySize, SMEM_TOTAL);
  mlp_all<<<NBLK_E + NBLK_T, NTH, SMEM_TOTAL>>>(
      h, src, dst, enorm, tsrc, tdi, tdj, nij, nik, cosv, sinv, mu,
      eW3, eb3, tW3, tb3, out);
}